// round 2
// baseline (speedup 1.0000x reference)
#include <cuda_runtime.h>
#include <math.h>
#include <stdint.h>

// Problem dims (fixed by the dataset)
#define BSROWS 4096   // B*S = 2*2048 candidate rows
#define HD     1024   // hidden dim
#define MSLOTS 8192   // memory slots

// ---------------- device scratch (no allocations allowed) ----------------
__device__ float g_buf[MSLOTS * HD];                      // updated memory buffer (32 MB)
__device__ float g_q[BSROWS * HD];                        // q projection        (16 MB)
__device__ float g_mk[MSLOTS * HD];                       // key projection      (32 MB)
__device__ float g_sc[(size_t)BSROWS * MSLOTS];           // scores / exp-probs  (128 MB)
__device__ float g_surp[BSROWS];                          // surprise per candidate
__device__ int   g_top_i[BSROWS];                         // candidates sorted by surprise desc
__device__ int   g_least[MSLOTS];                         // slots sorted by importance asc
__device__ float g_rinv[BSROWS];                          // 1/rowsum for softmax

// ---------------- helpers ----------------
__device__ __forceinline__ unsigned long long pack_kv(float key, unsigned idx) {
    unsigned u = __float_as_uint(key);
    u = (u & 0x80000000u) ? ~u : (u | 0x80000000u);   // total order matching float <
    return ((unsigned long long)u << 32) | idx;
}

__device__ __forceinline__ void bitonic_sort(unsigned long long* s, int n, int t, int nthreads) {
    for (int k = 2; k <= n; k <<= 1) {
        for (int j = k >> 1; j > 0; j >>= 1) {
            for (int i = t; i < n; i += nthreads) {
                int ixj = i ^ j;
                if (ixj > i) {
                    unsigned long long a = s[i], b = s[ixj];
                    bool up = ((i & k) == 0);
                    if ((a > b) == up) { s[i] = b; s[ixj] = a; }
                }
            }
            __syncthreads();
        }
    }
}

// ---------------- surprise: 2 * ||h||_2 per candidate row ----------------
__global__ void k_surprise(const float* __restrict__ h) {
    int row = blockIdx.x;
    int t = threadIdx.x;                         // 256 threads, 1 float4 each = 1024 floats
    const float4* p = (const float4*)(h + (size_t)row * HD);
    float4 v = p[t];
    float s = v.x * v.x + v.y * v.y + v.z * v.z + v.w * v.w;
    #pragma unroll
    for (int o = 16; o; o >>= 1) s += __shfl_xor_sync(0xffffffffu, s, o);
    __shared__ float ws[8];
    if ((t & 31) == 0) ws[t >> 5] = s;
    __syncthreads();
    if (t < 8) {
        float x = ws[t];
        #pragma unroll
        for (int o = 4; o; o >>= 1) x += __shfl_xor_sync(0xffu, x, o);
        if (t == 0) g_surp[row] = 2.0f * sqrtf(x);
    }
}

// ---------------- sort candidates by surprise desc (tie: idx asc) ----------------
__global__ void k_sort_surprise() {
    __shared__ unsigned long long sm[BSROWS];   // 32 KB
    int t = threadIdx.x;                        // 1024 threads
    for (int i = t; i < BSROWS; i += 1024) sm[i] = pack_kv(-g_surp[i], (unsigned)i);
    __syncthreads();
    bitonic_sort(sm, BSROWS, t, 1024);
    for (int i = t; i < BSROWS; i += 1024) g_top_i[i] = (int)(unsigned)sm[i];
}

// ---------------- sort slots by importance+noise asc (tie: idx asc) ----------------
__global__ void k_sort_least(const float* __restrict__ imp, const float* __restrict__ noise) {
    extern __shared__ unsigned long long dsm[]; // 64 KB dynamic
    int t = threadIdx.x;
    for (int i = t; i < MSLOTS; i += 1024) {
        float key = imp[i] + noise[i] * 1e-6f;  // bitwise-identical to reference key
        dsm[i] = pack_kv(key, (unsigned)i);
    }
    __syncthreads();
    bitonic_sort(dsm, MSLOTS, t, 1024);
    for (int i = t; i < MSLOTS; i += 1024) g_least[i] = (int)(unsigned)dsm[i];
}

// ---------------- copy original buffer into scratch ----------------
__global__ void k_copybuf(const float* __restrict__ src) {
    const float4* s = (const float4*)src;
    float4* d = (float4*)g_buf;
    size_t n = (size_t)MSLOTS * HD / 4;
    for (size_t i = blockIdx.x * 256ull + threadIdx.x; i < n; i += (size_t)gridDim.x * 256)
        d[i] = s[i];
}

// ---------------- scatter valid candidates into least-important slots ----------------
__global__ void k_scatter(const float* __restrict__ hidden) {
    int i = blockIdx.x;                 // rank in surprise-desc order, 0..4095
    int cand = g_top_i[i];
    if (g_surp[cand] > 64.0f) {         // strict: matches top_s > THRESH
        int slot = g_least[i];
        const float4* src = (const float4*)(hidden + (size_t)cand * HD);
        float4* dst = (float4*)(g_buf + (size_t)slot * HD);
        dst[threadIdx.x] = src[threadIdx.x];   // 256 * float4 = 1024 floats
    }
}

// ---------------- SGEMM NT: C[M,N] = alpha * A[M,K] * B[N,K]^T + bias ----------------
__global__ void __launch_bounds__(256, 2)
sgemm_nt(const float* __restrict__ A, const float* __restrict__ B,
         const float* __restrict__ bias, float* __restrict__ C,
         int N, int K, float alpha)
{
    __shared__ float As[8][128];
    __shared__ float Bs[8][128];
    const int tid = threadIdx.x;
    const int row0 = blockIdx.y * 128;
    const int col0 = blockIdx.x * 128;
    const int lr = tid >> 1;
    const int lk = (tid & 1) * 4;
    const int tm0 = (tid >> 4) * 8;
    const int tn0 = (tid & 15) * 8;
    const float* Ap = A + (size_t)(row0 + lr) * K + lk;
    const float* Bp = B + (size_t)(col0 + lr) * K + lk;
    float acc[8][8];
    #pragma unroll
    for (int m = 0; m < 8; m++)
        #pragma unroll
        for (int n = 0; n < 8; n++) acc[m][n] = 0.0f;

    for (int k0 = 0; k0 < K; k0 += 8) {
        float4 av = *(const float4*)(Ap + k0);
        float4 bv = *(const float4*)(Bp + k0);
        __syncthreads();
        As[lk + 0][lr] = av.x; As[lk + 1][lr] = av.y;
        As[lk + 2][lr] = av.z; As[lk + 3][lr] = av.w;
        Bs[lk + 0][lr] = bv.x; Bs[lk + 1][lr] = bv.y;
        Bs[lk + 2][lr] = bv.z; Bs[lk + 3][lr] = bv.w;
        __syncthreads();
        #pragma unroll
        for (int kk = 0; kk < 8; kk++) {
            float ra[8], rb[8];
            *(float4*)(ra)     = *(const float4*)&As[kk][tm0];
            *(float4*)(ra + 4) = *(const float4*)&As[kk][tm0 + 4];
            *(float4*)(rb)     = *(const float4*)&Bs[kk][tn0];
            *(float4*)(rb + 4) = *(const float4*)&Bs[kk][tn0 + 4];
            #pragma unroll
            for (int m = 0; m < 8; m++)
                #pragma unroll
                for (int n = 0; n < 8; n++)
                    acc[m][n] += ra[m] * rb[n];
        }
    }

    float rbias[8];
    #pragma unroll
    for (int n = 0; n < 8; n++) rbias[n] = bias ? bias[col0 + tn0 + n] : 0.0f;
    #pragma unroll
    for (int m = 0; m < 8; m++) {
        float* cp = C + (size_t)(row0 + tm0 + m) * N + col0 + tn0;
        float4 o0, o1;
        o0.x = acc[m][0] * alpha + rbias[0]; o0.y = acc[m][1] * alpha + rbias[1];
        o0.z = acc[m][2] * alpha + rbias[2]; o0.w = acc[m][3] * alpha + rbias[3];
        o1.x = acc[m][4] * alpha + rbias[4]; o1.y = acc[m][5] * alpha + rbias[5];
        o1.z = acc[m][6] * alpha + rbias[6]; o1.w = acc[m][7] * alpha + rbias[7];
        *(float4*)cp = o0;
        *(float4*)(cp + 4) = o1;
    }
}

// ---------------- SGEMM NN: C[M,N] = rowscale[m] * A[M,K] * B[K,N] ----------------
__global__ void __launch_bounds__(256, 2)
sgemm_nn(const float* __restrict__ A, const float* __restrict__ B,
         const float* __restrict__ rowscale, float* __restrict__ C,
         int N, int K)
{
    __shared__ float As[8][128];
    __shared__ float Bs[8][128];
    const int tid = threadIdx.x;
    const int row0 = blockIdx.y * 128;
    const int col0 = blockIdx.x * 128;
    const int lr = tid >> 1;
    const int lk = (tid & 1) * 4;
    const int bkr = tid >> 5;
    const int bn = (tid & 31) * 4;
    const int tm0 = (tid >> 4) * 8;
    const int tn0 = (tid & 15) * 8;
    const float* Ap = A + (size_t)(row0 + lr) * K + lk;
    const float* Bp = B + (size_t)bkr * N + col0 + bn;
    float acc[8][8];
    #pragma unroll
    for (int m = 0; m < 8; m++)
        #pragma unroll
        for (int n = 0; n < 8; n++) acc[m][n] = 0.0f;

    for (int k0 = 0; k0 < K; k0 += 8) {
        float4 av = *(const float4*)(Ap + k0);
        float4 bv = *(const float4*)(Bp + (size_t)k0 * N);
        __syncthreads();
        As[lk + 0][lr] = av.x; As[lk + 1][lr] = av.y;
        As[lk + 2][lr] = av.z; As[lk + 3][lr] = av.w;
        *(float4*)&Bs[bkr][bn] = bv;
        __syncthreads();
        #pragma unroll
        for (int kk = 0; kk < 8; kk++) {
            float ra[8], rb[8];
            *(float4*)(ra)     = *(const float4*)&As[kk][tm0];
            *(float4*)(ra + 4) = *(const float4*)&As[kk][tm0 + 4];
            *(float4*)(rb)     = *(const float4*)&Bs[kk][tn0];
            *(float4*)(rb + 4) = *(const float4*)&Bs[kk][tn0 + 4];
            #pragma unroll
            for (int m = 0; m < 8; m++)
                #pragma unroll
                for (int n = 0; n < 8; n++)
                    acc[m][n] += ra[m] * rb[n];
        }
    }

    #pragma unroll
    for (int m = 0; m < 8; m++) {
        int gr = row0 + tm0 + m;
        float rs = rowscale ? rowscale[gr] : 1.0f;
        float* cp = C + (size_t)gr * N + col0 + tn0;
        float4 o0, o1;
        o0.x = acc[m][0] * rs; o0.y = acc[m][1] * rs;
        o0.z = acc[m][2] * rs; o0.w = acc[m][3] * rs;
        o1.x = acc[m][4] * rs; o1.y = acc[m][5] * rs;
        o1.z = acc[m][6] * rs; o1.w = acc[m][7] * rs;
        *(float4*)cp = o0;
        *(float4*)(cp + 4) = o1;
    }
}

// ---------------- row softmax: write exp(x-max) in place + 1/rowsum ----------------
__global__ void k_softmax(float* __restrict__ S, float* __restrict__ rinv, int n) {
    int row = blockIdx.x;
    float* p = S + (size_t)row * n;
    int t = threadIdx.x;                // 256 threads
    __shared__ float sred[8];
    __shared__ float sbc;

    float m = -3.4e38f;
    for (int i = 4 * t; i < n; i += 1024) {
        float4 v = *(const float4*)(p + i);
        m = fmaxf(m, fmaxf(fmaxf(v.x, v.y), fmaxf(v.z, v.w)));
    }
    #pragma unroll
    for (int o = 16; o; o >>= 1) m = fmaxf(m, __shfl_xor_sync(0xffffffffu, m, o));
    if ((t & 31) == 0) sred[t >> 5] = m;
    __syncthreads();
    if (t < 8) {
        float x = sred[t];
        #pragma unroll
        for (int o = 4; o; o >>= 1) x = fmaxf(x, __shfl_xor_sync(0xffu, x, o));
        if (t == 0) sbc = x;
    }
    __syncthreads();
    m = sbc;
    __syncthreads();

    float sum = 0.0f;
    for (int i = 4 * t; i < n; i += 1024) {
        float4 v = *(const float4*)(p + i);
        v.x = expf(v.x - m); v.y = expf(v.y - m);
        v.z = expf(v.z - m); v.w = expf(v.w - m);
        sum += v.x + v.y + v.z + v.w;
        *(float4*)(p + i) = v;
    }
    #pragma unroll
    for (int o = 16; o; o >>= 1) sum += __shfl_xor_sync(0xffffffffu, sum, o);
    if ((t & 31) == 0) sred[t >> 5] = sum;
    __syncthreads();
    if (t == 0) {
        float x = 0.0f;
        #pragma unroll
        for (int w = 0; w < 8; w++) x += sred[w];
        rinv[row] = 1.0f / x;
    }
}

// ---------------- host launch ----------------
extern "C" void kernel_launch(void* const* d_in, const int* in_sizes, int n_in,
                              void* d_out, int out_size) {
    const float* hidden = (const float*)d_in[0];
    const float* membuf = (const float*)d_in[1];
    const float* imp    = (const float*)d_in[2];
    const float* Wq     = (const float*)d_in[3];
    const float* bq     = (const float*)d_in[4];
    const float* Wk     = (const float*)d_in[5];
    const float* bk     = (const float*)d_in[6];
    const float* noise  = (const float*)d_in[7];
    float* out = (float*)d_out;

    cudaFuncSetAttribute(k_sort_least, cudaFuncAttributeMaxDynamicSharedMemorySize, 65536);

    void *p_buf, *p_q, *p_mk, *p_sc, *p_rinv;
    cudaGetSymbolAddress(&p_buf, g_buf);
    cudaGetSymbolAddress(&p_q,   g_q);
    cudaGetSymbolAddress(&p_mk,  g_mk);
    cudaGetSymbolAddress(&p_sc,  g_sc);
    cudaGetSymbolAddress(&p_rinv, g_rinv);

    // 1. surprise + sorts + memory update
    k_surprise<<<BSROWS, 256>>>(hidden);
    k_sort_surprise<<<1, 1024>>>();
    k_sort_least<<<1, 1024, 65536>>>(imp, noise);
    k_copybuf<<<2048, 256>>>(membuf);
    k_scatter<<<BSROWS, 256>>>(hidden);

    // 2. projections: q = hidden @ Wq^T + bq ; mk = buf @ Wk^T + bk
    sgemm_nt<<<dim3(HD / 128, BSROWS / 128), 256>>>(hidden, Wq, bq, (float*)p_q, HD, HD, 1.0f);
    sgemm_nt<<<dim3(HD / 128, MSLOTS / 128), 256>>>((const float*)p_buf, Wk, bk, (float*)p_mk, HD, HD, 1.0f);

    // 3. scores = q @ mk^T / sqrt(H)
    sgemm_nt<<<dim3(MSLOTS / 128, BSROWS / 128), 256>>>((const float*)p_q, (const float*)p_mk,
                                                        nullptr, (float*)p_sc, MSLOTS, HD, 0.03125f);

    // 4. softmax rows (exp + inverse rowsum; normalization folded into next GEMM)
    k_softmax<<<BSROWS, 256>>>((float*)p_sc, (float*)p_rinv, MSLOTS);

    // 5. retrieved = attn @ buf -> d_out
    sgemm_nn<<<dim3(HD / 128, BSROWS / 128), 256>>>((const float*)p_sc, (const float*)p_buf,
                                                    (const float*)p_rinv, out, HD, MSLOTS);
}

// round 5
// speedup vs baseline: 1.3957x; 1.3957x over previous
#include <cuda_runtime.h>
#include <cuda_bf16.h>
#include <math.h>
#include <stdint.h>

#define BSROWS 4096   // B*S
#define HD     1024
#define MSLOTS 8192

// ---------------- device scratch (no allocations allowed) ----------------
__device__ float g_buf[MSLOTS * HD];                         // updated memory (fp32)
__device__ float g_sc[(size_t)BSROWS * MSLOTS];              // scores fp32 (128 MB)
__device__ __nv_bfloat16 g_hsp [BSROWS * 2 * HD];            // hidden split   [4096,2048]
__device__ __nv_bfloat16 g_wqsp[HD * 2 * HD];                // Wq split       [1024,2048]
__device__ __nv_bfloat16 g_wksp[HD * 2 * HD];                // Wk split
__device__ __nv_bfloat16 g_bufsp[MSLOTS * 2 * HD];           // buf split      [8192,2048]
__device__ __nv_bfloat16 g_qsp [BSROWS * 2 * HD];            // q split
__device__ __nv_bfloat16 g_mksp[MSLOTS * 2 * HD];            // mk split
__device__ __nv_bfloat16 g_attnsp[(size_t)BSROWS * 2 * MSLOTS]; // attn split [4096,16384]
__device__ __nv_bfloat16 g_bTsp[HD * 2 * MSLOTS];            // buf^T split    [1024,16384]
__device__ float g_surp[BSROWS];
__device__ int   g_top_i[BSROWS];
__device__ int   g_least[MSLOTS];
__device__ float g_rinv[BSROWS];

// ---------------- PTX helpers (base sm_103 ISA only: cp.async/ldmatrix/mma) ----
__device__ __forceinline__ uint32_t smem_u32(const void* p) {
    uint32_t a;
    asm("{ .reg .u64 t; cvta.to.shared.u64 t, %1; cvt.u32.u64 %0, t; }" : "=r"(a) : "l"(p));
    return a;
}
__device__ __forceinline__ void cpasync16(uint32_t dst, const void* src) {
    asm volatile("cp.async.cg.shared.global [%0], [%1], 16;"
                 :: "r"(dst), "l"(__cvta_generic_to_global(src)) : "memory");
}
__device__ __forceinline__ void cp_commit() {
    asm volatile("cp.async.commit_group;" ::: "memory");
}
__device__ __forceinline__ void cp_wait3() {
    asm volatile("cp.async.wait_group 3;" ::: "memory");
}
__device__ __forceinline__ void ldsm4(uint32_t& r0, uint32_t& r1, uint32_t& r2, uint32_t& r3,
                                      uint32_t addr) {
    asm volatile("ldmatrix.sync.aligned.m8n8.x4.shared.b16 {%0,%1,%2,%3}, [%4];"
                 : "=r"(r0), "=r"(r1), "=r"(r2), "=r"(r3) : "r"(addr));
}
__device__ __forceinline__ void mma16816(float* c, const uint32_t* a, const uint32_t* b) {
    asm volatile(
        "mma.sync.aligned.m16n8k16.row.col.f32.bf16.bf16.f32 "
        "{%0,%1,%2,%3}, {%4,%5,%6,%7}, {%8,%9}, {%0,%1,%2,%3};"
        : "+f"(c[0]), "+f"(c[1]), "+f"(c[2]), "+f"(c[3])
        : "r"(a[0]), "r"(a[1]), "r"(a[2]), "r"(a[3]), "r"(b[0]), "r"(b[1]));
}
__device__ __forceinline__ void split2(float v, __nv_bfloat16& h, __nv_bfloat16& l) {
    h = __float2bfloat16(v);
    l = __float2bfloat16(v - __bfloat162float(h));
}

// ---------------- HMMA GEMM: C[M,N] = A[M,*] (x) B[N,*]^T, split-bf16, 3 segments ----
// Smem tile: A 128x32 + B 128x32 bf16, padded row stride 40 elems (80B, odd*16B ->
// ldmatrix phase-conflict-free). 4 stages, 20480B each.
#define TSTRIDE 40
#define STAGE_BYTES (128 * TSTRIDE * 2 * 2)   // 20480
#define GSMEM_TOTAL (4 * STAGE_BYTES)         // 81920

__global__ void __launch_bounds__(256, 1)
gemm_sp(const __nv_bfloat16* __restrict__ A, const __nv_bfloat16* __restrict__ B,
        int ldA, int ldB, int Kseg,
        const float* __restrict__ bias, const float* __restrict__ rowscale, float alpha,
        float* __restrict__ outF, __nv_bfloat16* __restrict__ outS, int ldOut)
{
    extern __shared__ char smem[];
    const uint32_t sb = smem_u32(smem);
    const int tid = threadIdx.x;
    const int wid = tid >> 5;
    const int lane = tid & 31;
    const int wm = wid & 1;        // 2 warps over M (64 rows each)
    const int wn = wid >> 1;       // 4 warps over N (32 cols each)
    const int row0 = blockIdx.y * 128;
    const int col0 = blockIdx.x * 128;
    const int kch = Kseg >> 5;     // 32-wide chunks per segment
    const int C = 3 * kch;         // 3 segments: hi*hi, hi*lo, lo*hi

    const int lr = tid >> 1;       // load row 0..127
    const int lh = tid & 1;        // load half (cols 0-15 / 16-31)

    auto load_chunk = [&](int c) {
        const int s = c & 3;
        const int seg = c / kch;
        const int kcol = (c - seg * kch) << 5;
        const int aoff = (seg == 2) ? Kseg : 0;
        const int boff = (seg == 1) ? Kseg : 0;
        const uint32_t st = sb + s * STAGE_BYTES;
        const __nv_bfloat16* ag = A + (size_t)(row0 + lr) * ldA + kcol + aoff + lh * 16;
        const __nv_bfloat16* bg = B + (size_t)(col0 + lr) * ldB + kcol + boff + lh * 16;
        const uint32_t doff = (lr * TSTRIDE + lh * 16) * 2;
        cpasync16(st + doff, ag);
        cpasync16(st + doff + 16, ag + 8);
        cpasync16(st + 10240 + doff, bg);
        cpasync16(st + 10240 + doff + 16, bg + 8);
        cp_commit();
    };

    float acc[4][4][4];
    #pragma unroll
    for (int mt = 0; mt < 4; mt++)
        #pragma unroll
        for (int nt = 0; nt < 4; nt++)
            #pragma unroll
            for (int i = 0; i < 4; i++) acc[mt][nt][i] = 0.0f;

    load_chunk(0); load_chunk(1); load_chunk(2);

    for (int c = 0; c < C; c++) {
        if (c + 3 < C) load_chunk(c + 3);
        cp_wait3();
        __syncthreads();
        const uint32_t aB = sb + (c & 3) * STAGE_BYTES;
        const uint32_t bB = aB + 10240;
        #pragma unroll
        for (int ks = 0; ks < 2; ks++) {
            uint32_t af[4][4], bf[4][2];
            #pragma unroll
            for (int mt = 0; mt < 4; mt++) {
                int row = wm * 64 + mt * 16 + (lane & 15);
                int col = ks * 16 + ((lane >> 4) << 3);
                ldsm4(af[mt][0], af[mt][1], af[mt][2], af[mt][3],
                      aB + (row * TSTRIDE + col) * 2);
            }
            #pragma unroll
            for (int nt2 = 0; nt2 < 2; nt2++) {
                int row = wn * 32 + nt2 * 16 + ((lane >> 4) << 3) + (lane & 7);
                int col = ks * 16 + (((lane >> 3) & 1) << 3);
                ldsm4(bf[nt2 * 2][0], bf[nt2 * 2][1], bf[nt2 * 2 + 1][0], bf[nt2 * 2 + 1][1],
                      bB + (row * TSTRIDE + col) * 2);
            }
            #pragma unroll
            for (int mt = 0; mt < 4; mt++)
                #pragma unroll
                for (int nt = 0; nt < 4; nt++)
                    mma16816(acc[mt][nt], af[mt], bf[nt]);
        }
        __syncthreads();
    }

    // ---- epilogue ----
    const int Kout = ldOut >> 1;
    #pragma unroll
    for (int mt = 0; mt < 4; mt++) {
        const int r0g = row0 + wm * 64 + mt * 16 + (lane >> 2);
        #pragma unroll
        for (int half = 0; half < 2; half++) {
            const int rg = r0g + half * 8;
            const float rs = rowscale ? rowscale[rg] : 1.0f;
            #pragma unroll
            for (int nt = 0; nt < 4; nt++) {
                const int cg = col0 + wn * 32 + nt * 8 + ((lane & 3) << 1);
                float v0 = acc[mt][nt][half * 2 + 0] * alpha;
                float v1 = acc[mt][nt][half * 2 + 1] * alpha;
                if (bias) { v0 += bias[cg]; v1 += bias[cg + 1]; }
                v0 *= rs; v1 *= rs;
                if (outF) {
                    *(float2*)(outF + (size_t)rg * ldOut + cg) = make_float2(v0, v1);
                } else {
                    __nv_bfloat16 h0, l0, h1, l1;
                    split2(v0, h0, l0); split2(v1, h1, l1);
                    __nv_bfloat162 hp, lp;
                    hp.x = h0; hp.y = h1; lp.x = l0; lp.y = l1;
                    *(__nv_bfloat162*)(outS + (size_t)rg * ldOut + cg) = hp;
                    *(__nv_bfloat162*)(outS + (size_t)rg * ldOut + Kout + cg) = lp;
                }
            }
        }
    }
}

// ---------------- pre/post kernels ----------------
__device__ __forceinline__ unsigned long long pack_kv(float key, unsigned idx) {
    unsigned u = __float_as_uint(key);
    u = (u & 0x80000000u) ? ~u : (u | 0x80000000u);
    return ((unsigned long long)u << 32) | idx;
}
__device__ __forceinline__ void bitonic_sort(unsigned long long* s, int n, int t, int nt) {
    for (int k = 2; k <= n; k <<= 1)
        for (int j = k >> 1; j > 0; j >>= 1) {
            for (int i = t; i < n; i += nt) {
                int ixj = i ^ j;
                if (ixj > i) {
                    unsigned long long a = s[i], b = s[ixj];
                    bool up = ((i & k) == 0);
                    if ((a > b) == up) { s[i] = b; s[ixj] = a; }
                }
            }
            __syncthreads();
        }
}

__global__ void k_surprise(const float* __restrict__ h) {
    int row = blockIdx.x, t = threadIdx.x;
    const float4* p = (const float4*)(h + (size_t)row * HD);
    float4 v = p[t];
    float s = v.x * v.x + v.y * v.y + v.z * v.z + v.w * v.w;
    #pragma unroll
    for (int o = 16; o; o >>= 1) s += __shfl_xor_sync(0xffffffffu, s, o);
    __shared__ float ws[8];
    if ((t & 31) == 0) ws[t >> 5] = s;
    __syncthreads();
    if (t < 8) {
        float x = ws[t];
        #pragma unroll
        for (int o = 4; o; o >>= 1) x += __shfl_xor_sync(0xffu, x, o);
        if (t == 0) g_surp[row] = 2.0f * sqrtf(x);
    }
}

__global__ void k_sort_surprise() {
    __shared__ unsigned long long sm[BSROWS];
    int t = threadIdx.x;
    for (int i = t; i < BSROWS; i += 1024) sm[i] = pack_kv(-g_surp[i], (unsigned)i);
    __syncthreads();
    bitonic_sort(sm, BSROWS, t, 1024);
    for (int i = t; i < BSROWS; i += 1024) g_top_i[i] = (int)(unsigned)sm[i];
}

__global__ void k_sort_least(const float* __restrict__ imp, const float* __restrict__ noise) {
    extern __shared__ unsigned long long dsm[];
    int t = threadIdx.x;
    for (int i = t; i < MSLOTS; i += 1024)
        dsm[i] = pack_kv(imp[i] + noise[i] * 1e-6f, (unsigned)i);
    __syncthreads();
    bitonic_sort(dsm, MSLOTS, t, 1024);
    for (int i = t; i < MSLOTS; i += 1024) g_least[i] = (int)(unsigned)dsm[i];
}

__global__ void k_copybuf(const float* __restrict__ src) {
    const float4* s = (const float4*)src;
    float4* d = (float4*)g_buf;
    size_t n = (size_t)MSLOTS * HD / 4;
    for (size_t i = blockIdx.x * 256ull + threadIdx.x; i < n; i += (size_t)gridDim.x * 256)
        d[i] = s[i];
}

__global__ void k_scatter(const float* __restrict__ hidden) {
    int i = blockIdx.x;
    int cand = g_top_i[i];
    if (g_surp[cand] > 64.0f) {
        int slot = g_least[i];
        const float4* src = (const float4*)(hidden + (size_t)cand * HD);
        float4* dst = (float4*)(g_buf + (size_t)slot * HD);
        dst[threadIdx.x] = src[threadIdx.x];
    }
}

// fp32 [R,1024] -> split bf16 [R,2048]
__global__ void k_split1024(const float* __restrict__ in, __nv_bfloat16* __restrict__ out,
                            int total) {
    for (int e = blockIdx.x * 256 + threadIdx.x; e < total; e += gridDim.x * 256) {
        int r = e >> 10, k = e & 1023;
        __nv_bfloat16 h, l;
        split2(in[e], h, l);
        out[((size_t)r << 11) + k] = h;
        out[((size_t)r << 11) + 1024 + k] = l;
    }
}

// transpose + split: buf[8192,1024] -> bT[1024,16384]
__global__ void k_tsplit(const float* __restrict__ in, __nv_bfloat16* __restrict__ out) {
    __shared__ float tile[32][33];
    int bc = blockIdx.x * 32, br = blockIdx.y * 32;
    int tx = threadIdx.x, ty = threadIdx.y;   // 32x8
    #pragma unroll
    for (int i = 0; i < 32; i += 8)
        tile[ty + i][tx] = in[(size_t)(br + ty + i) * 1024 + bc + tx];
    __syncthreads();
    #pragma unroll
    for (int i = 0; i < 32; i += 8) {
        __nv_bfloat16 h, l;
        split2(tile[tx][ty + i], h, l);
        size_t o = (size_t)(bc + ty + i) * 16384 + br + tx;
        out[o] = h;
        out[o + 8192] = l;
    }
}

// softmax: scores fp32 -> unnormalized exp as split bf16 + 1/rowsum
__global__ void k_softmax() {
    int row = blockIdx.x, t = threadIdx.x;   // 256 threads
    const float* p = g_sc + (size_t)row * MSLOTS;
    __nv_bfloat16* a = g_attnsp + (size_t)row * (2 * MSLOTS);
    __shared__ float sred[8];
    __shared__ float sbc;

    float m = -3.4e38f;
    for (int i = 4 * t; i < MSLOTS; i += 1024) {
        float4 v = *(const float4*)(p + i);
        m = fmaxf(m, fmaxf(fmaxf(v.x, v.y), fmaxf(v.z, v.w)));
    }
    #pragma unroll
    for (int o = 16; o; o >>= 1) m = fmaxf(m, __shfl_xor_sync(0xffffffffu, m, o));
    if ((t & 31) == 0) sred[t >> 5] = m;
    __syncthreads();
    if (t < 8) {
        float x = sred[t];
        #pragma unroll
        for (int o = 4; o; o >>= 1) x = fmaxf(x, __shfl_xor_sync(0xffu, x, o));
        if (t == 0) sbc = x;
    }
    __syncthreads();
    m = sbc;
    __syncthreads();

    float sum = 0.0f;
    for (int i = 4 * t; i < MSLOTS; i += 1024) {
        float4 v = *(const float4*)(p + i);
        float e0 = expf(v.x - m), e1 = expf(v.y - m), e2 = expf(v.z - m), e3 = expf(v.w - m);
        sum += e0 + e1 + e2 + e3;
        __align__(8) __nv_bfloat16 h[4], l[4];
        split2(e0, h[0], l[0]); split2(e1, h[1], l[1]);
        split2(e2, h[2], l[2]); split2(e3, h[3], l[3]);
        *(uint2*)(a + i) = *(uint2*)h;
        *(uint2*)(a + MSLOTS + i) = *(uint2*)l;
    }
    #pragma unroll
    for (int o = 16; o; o >>= 1) sum += __shfl_xor_sync(0xffffffffu, sum, o);
    if ((t & 31) == 0) sred[t >> 5] = sum;
    __syncthreads();
    if (t == 0) {
        float x = 0.0f;
        #pragma unroll
        for (int w = 0; w < 8; w++) x += sred[w];
        g_rinv[row] = 1.0f / x;
    }
}

// ---------------- host launch ----------------
extern "C" void kernel_launch(void* const* d_in, const int* in_sizes, int n_in,
                              void* d_out, int out_size) {
    const float* hidden = (const float*)d_in[0];
    const float* membuf = (const float*)d_in[1];
    const float* imp    = (const float*)d_in[2];
    const float* Wq     = (const float*)d_in[3];
    const float* bq     = (const float*)d_in[4];
    const float* Wk     = (const float*)d_in[5];
    const float* bk     = (const float*)d_in[6];
    const float* noise  = (const float*)d_in[7];
    float* out = (float*)d_out;

    cudaFuncSetAttribute(k_sort_least, cudaFuncAttributeMaxDynamicSharedMemorySize, 65536);
    cudaFuncSetAttribute(gemm_sp, cudaFuncAttributeMaxDynamicSharedMemorySize, GSMEM_TOTAL);

    void *p_buf, *p_hsp, *p_wqsp, *p_wksp, *p_bufsp, *p_qsp, *p_mksp, *p_attn, *p_bT, *p_sc, *p_rinv;
    cudaGetSymbolAddress(&p_buf, g_buf);
    cudaGetSymbolAddress(&p_hsp, g_hsp);
    cudaGetSymbolAddress(&p_wqsp, g_wqsp);
    cudaGetSymbolAddress(&p_wksp, g_wksp);
    cudaGetSymbolAddress(&p_bufsp, g_bufsp);
    cudaGetSymbolAddress(&p_qsp, g_qsp);
    cudaGetSymbolAddress(&p_mksp, g_mksp);
    cudaGetSymbolAddress(&p_attn, g_attnsp);
    cudaGetSymbolAddress(&p_bT, g_bTsp);
    cudaGetSymbolAddress(&p_sc, g_sc);
    cudaGetSymbolAddress(&p_rinv, g_rinv);

    // 1. surprise + sorts + memory update
    k_surprise<<<BSROWS, 256>>>(hidden);
    k_sort_surprise<<<1, 1024>>>();
    k_sort_least<<<1, 1024, 65536>>>(imp, noise);
    k_copybuf<<<2048, 256>>>(membuf);
    k_scatter<<<BSROWS, 256>>>(hidden);

    // 2. split conversions
    k_split1024<<<2048, 256>>>(hidden, (__nv_bfloat16*)p_hsp, BSROWS * HD);
    k_split1024<<<1024, 256>>>(Wq, (__nv_bfloat16*)p_wqsp, HD * HD);
    k_split1024<<<1024, 256>>>(Wk, (__nv_bfloat16*)p_wksp, HD * HD);
    k_split1024<<<2048, 256>>>((const float*)p_buf, (__nv_bfloat16*)p_bufsp, MSLOTS * HD);
    k_tsplit<<<dim3(32, 256), dim3(32, 8)>>>((const float*)p_buf, (__nv_bfloat16*)p_bT);

    // 3. q = hidden @ Wq^T + bq  -> split bf16
    gemm_sp<<<dim3(HD / 128, BSROWS / 128), 256, GSMEM_TOTAL>>>(
        (const __nv_bfloat16*)p_hsp, (const __nv_bfloat16*)p_wqsp, 2 * HD, 2 * HD, HD,
        bq, nullptr, 1.0f, nullptr, (__nv_bfloat16*)p_qsp, 2 * HD);

    // 4. mk = buf @ Wk^T + bk -> split bf16
    gemm_sp<<<dim3(HD / 128, MSLOTS / 128), 256, GSMEM_TOTAL>>>(
        (const __nv_bfloat16*)p_bufsp, (const __nv_bfloat16*)p_wksp, 2 * HD, 2 * HD, HD,
        bk, nullptr, 1.0f, nullptr, (__nv_bfloat16*)p_mksp, 2 * HD);

    // 5. scores = q @ mk^T / 32 -> fp32
    gemm_sp<<<dim3(MSLOTS / 128, BSROWS / 128), 256, GSMEM_TOTAL>>>(
        (const __nv_bfloat16*)p_qsp, (const __nv_bfloat16*)p_mksp, 2 * HD, 2 * HD, HD,
        nullptr, nullptr, 0.03125f, (float*)p_sc, nullptr, MSLOTS);

    // 6. softmax -> unnormalized exp split bf16 + 1/rowsum
    k_softmax<<<BSROWS, 256>>>();

    // 7. retrieved = (exp @ buf) * rinv -> d_out fp32
    gemm_sp<<<dim3(HD / 128, BSROWS / 128), 256, GSMEM_TOTAL>>>(
        (const __nv_bfloat16*)p_attn, (const __nv_bfloat16*)p_bT, 2 * MSLOTS, 2 * MSLOTS, MSLOTS,
        nullptr, (const float*)p_rinv, 1.0f, out, nullptr, HD);
}

// round 6
// speedup vs baseline: 2.1512x; 1.5413x over previous
#include <cuda_runtime.h>
#include <cuda_bf16.h>
#include <math.h>
#include <stdint.h>

#define BSROWS 4096   // B*S
#define HD     1024
#define MSLOTS 8192

// ---------------- device scratch (no allocations allowed) ----------------
__device__ float g_buf[MSLOTS * HD];                         // updated memory (fp32)
__device__ float g_sc[(size_t)BSROWS * MSLOTS];              // scores fp32 (128 MB)
__device__ __nv_bfloat16 g_hsp [BSROWS * 2 * HD];            // hidden split   [4096,2048]
__device__ __nv_bfloat16 g_wqsp[HD * 2 * HD];                // Wq split       [1024,2048]
__device__ __nv_bfloat16 g_wksp[HD * 2 * HD];                // Wk split
__device__ __nv_bfloat16 g_bufsp[MSLOTS * 2 * HD];           // buf split      [8192,2048]
__device__ __nv_bfloat16 g_qsp [BSROWS * 2 * HD];            // q split
__device__ __nv_bfloat16 g_mksp[MSLOTS * 2 * HD];            // mk split
__device__ __nv_bfloat16 g_attnsp[(size_t)BSROWS * 2 * MSLOTS]; // attn split [4096,16384]
__device__ __nv_bfloat16 g_bTsp[HD * 2 * MSLOTS];            // buf^T split    [1024,16384]
__device__ float g_surp[BSROWS];
__device__ int   g_top_i[BSROWS];
__device__ int   g_least[MSLOTS];
__device__ float g_rinv[BSROWS];

// ---------------- PTX helpers (base sm_103 ISA only) ----------------
__device__ __forceinline__ uint32_t smem_u32(const void* p) {
    uint32_t a;
    asm("{ .reg .u64 t; cvta.to.shared.u64 t, %1; cvt.u32.u64 %0, t; }" : "=r"(a) : "l"(p));
    return a;
}
__device__ __forceinline__ void cpasync16(uint32_t dst, const void* src) {
    asm volatile("cp.async.cg.shared.global [%0], [%1], 16;"
                 :: "r"(dst), "l"(__cvta_generic_to_global(src)) : "memory");
}
__device__ __forceinline__ void cp_commit() {
    asm volatile("cp.async.commit_group;" ::: "memory");
}
__device__ __forceinline__ void cp_wait2() {
    asm volatile("cp.async.wait_group 2;" ::: "memory");
}
__device__ __forceinline__ void ldsm4(uint32_t& r0, uint32_t& r1, uint32_t& r2, uint32_t& r3,
                                      uint32_t addr) {
    asm volatile("ldmatrix.sync.aligned.m8n8.x4.shared.b16 {%0,%1,%2,%3}, [%4];"
                 : "=r"(r0), "=r"(r1), "=r"(r2), "=r"(r3) : "r"(addr));
}
__device__ __forceinline__ void mma16816(float* c, const uint32_t* a, const uint32_t* b) {
    asm volatile(
        "mma.sync.aligned.m16n8k16.row.col.f32.bf16.bf16.f32 "
        "{%0,%1,%2,%3}, {%4,%5,%6,%7}, {%8,%9}, {%0,%1,%2,%3};"
        : "+f"(c[0]), "+f"(c[1]), "+f"(c[2]), "+f"(c[3])
        : "r"(a[0]), "r"(a[1]), "r"(a[2]), "r"(a[3]), "r"(b[0]), "r"(b[1]));
}
__device__ __forceinline__ void split2(float v, __nv_bfloat16& h, __nv_bfloat16& l) {
    h = __float2bfloat16(v);
    l = __float2bfloat16(v - __bfloat162float(h));
}

// ---------------- HMMA GEMM: C[M,N] = A[M,*] (x) B[N,*]^T, split-bf16, 3 segments ----
// Tile 128M x 256N, BK=64, 3 stages. Smem row stride 72 elems (144B = odd*16B ->
// ldmatrix phase-conflict-free). Stage: A 128x72x2 (18432B) + B 256x72x2 (36864B).
#define TSTRIDE 72
#define A_BYTES (128 * TSTRIDE * 2)            // 18432
#define STAGE_BYTES (A_BYTES + 256 * TSTRIDE * 2)  // 55296
#define GSMEM_TOTAL (3 * STAGE_BYTES)          // 165888

__global__ void __launch_bounds__(256, 1)
gemm_sp(const __nv_bfloat16* __restrict__ A, const __nv_bfloat16* __restrict__ B,
        int ldA, int ldB, int Kseg,
        const float* __restrict__ bias, const float* __restrict__ rowscale, float alpha,
        float* __restrict__ outF, __nv_bfloat16* __restrict__ outS, int ldOut)
{
    extern __shared__ char smem[];
    const uint32_t sb = smem_u32(smem);
    const int tid = threadIdx.x;
    const int wid = tid >> 5;
    const int lane = tid & 31;
    const int wm = wid & 1;        // 2 warps over M (64 rows each)
    const int wn = wid >> 1;       // 4 warps over N (64 cols each)
    const int row0 = blockIdx.y * 128;
    const int col0 = blockIdx.x * 256;
    const int kch = Kseg >> 6;     // 64-wide chunks per segment
    const int C = 3 * kch;         // segments: hi*hi, hi*lo, lo*hi

    // producer mapping: 16B units; A 1024 units (4/thread), B 2048 units (8/thread)
    auto load_chunk = [&](int c) {
        const int s = c % 3;
        const int seg = c / kch;
        const int kcol = (c - seg * kch) << 6;
        const int aoff = (seg == 2) ? Kseg : 0;
        const int boff = (seg == 1) ? Kseg : 0;
        const uint32_t st = sb + s * STAGE_BYTES;
        #pragma unroll
        for (int i = 0; i < 4; i++) {
            int u = tid + (i << 8);
            int r = u >> 3, uc = u & 7;
            cpasync16(st + r * (TSTRIDE * 2) + uc * 16,
                      A + (size_t)(row0 + r) * ldA + kcol + aoff + uc * 8);
        }
        #pragma unroll
        for (int i = 0; i < 8; i++) {
            int u = tid + (i << 8);
            int r = u >> 3, uc = u & 7;
            cpasync16(st + A_BYTES + r * (TSTRIDE * 2) + uc * 16,
                      B + (size_t)(col0 + r) * ldB + kcol + boff + uc * 8);
        }
    };

    float acc[4][8][4];
    #pragma unroll
    for (int mt = 0; mt < 4; mt++)
        #pragma unroll
        for (int nt = 0; nt < 8; nt++)
            #pragma unroll
            for (int i = 0; i < 4; i++) acc[mt][nt][i] = 0.0f;

    load_chunk(0); cp_commit();
    load_chunk(1); cp_commit();

    for (int c = 0; c < C; c++) {
        if (c + 2 < C) load_chunk(c + 2);
        cp_commit();                      // unconditional: keeps wait_group exact in tail
        cp_wait2();
        __syncthreads();
        const uint32_t aB = sb + (c % 3) * STAGE_BYTES;
        const uint32_t bB = aB + A_BYTES;
        #pragma unroll
        for (int ks = 0; ks < 4; ks++) {
            uint32_t af[4][4], bf[8][2];
            #pragma unroll
            for (int mt = 0; mt < 4; mt++) {
                int row = wm * 64 + mt * 16 + (lane & 15);
                int col = ks * 16 + ((lane >> 4) << 3);
                ldsm4(af[mt][0], af[mt][1], af[mt][2], af[mt][3],
                      aB + (row * TSTRIDE + col) * 2);
            }
            #pragma unroll
            for (int nt2 = 0; nt2 < 4; nt2++) {
                int row = wn * 64 + nt2 * 16 + ((lane >> 4) << 3) + (lane & 7);
                int col = ks * 16 + (((lane >> 3) & 1) << 3);
                ldsm4(bf[nt2 * 2][0], bf[nt2 * 2][1], bf[nt2 * 2 + 1][0], bf[nt2 * 2 + 1][1],
                      bB + (row * TSTRIDE + col) * 2);
            }
            #pragma unroll
            for (int mt = 0; mt < 4; mt++)
                #pragma unroll
                for (int nt = 0; nt < 8; nt++)
                    mma16816(acc[mt][nt], af[mt], bf[nt]);
        }
        __syncthreads();
    }

    // ---- epilogue ----
    const int Kout = ldOut >> 1;
    #pragma unroll
    for (int mt = 0; mt < 4; mt++) {
        const int r0g = row0 + wm * 64 + mt * 16 + (lane >> 2);
        #pragma unroll
        for (int half = 0; half < 2; half++) {
            const int rg = r0g + half * 8;
            const float rs = rowscale ? rowscale[rg] : 1.0f;
            #pragma unroll
            for (int nt = 0; nt < 8; nt++) {
                const int cg = col0 + wn * 64 + nt * 8 + ((lane & 3) << 1);
                float v0 = acc[mt][nt][half * 2 + 0] * alpha;
                float v1 = acc[mt][nt][half * 2 + 1] * alpha;
                if (bias) { v0 += bias[cg]; v1 += bias[cg + 1]; }
                v0 *= rs; v1 *= rs;
                if (outF) {
                    *(float2*)(outF + (size_t)rg * ldOut + cg) = make_float2(v0, v1);
                } else {
                    __nv_bfloat16 h0, l0, h1, l1;
                    split2(v0, h0, l0); split2(v1, h1, l1);
                    __nv_bfloat162 hp, lp;
                    hp.x = h0; hp.y = h1; lp.x = l0; lp.y = l1;
                    *(__nv_bfloat162*)(outS + (size_t)rg * ldOut + cg) = hp;
                    *(__nv_bfloat162*)(outS + (size_t)rg * ldOut + Kout + cg) = lp;
                }
            }
        }
    }
}

// ---------------- pre/post kernels ----------------
__device__ __forceinline__ unsigned long long pack_kv(float key, unsigned idx) {
    unsigned u = __float_as_uint(key);
    u = (u & 0x80000000u) ? ~u : (u | 0x80000000u);
    return ((unsigned long long)u << 32) | idx;
}
__device__ __forceinline__ void bitonic_sort(unsigned long long* s, int n, int t, int nt) {
    for (int k = 2; k <= n; k <<= 1)
        for (int j = k >> 1; j > 0; j >>= 1) {
            for (int i = t; i < n; i += nt) {
                int ixj = i ^ j;
                if (ixj > i) {
                    unsigned long long a = s[i], b = s[ixj];
                    bool up = ((i & k) == 0);
                    if ((a > b) == up) { s[i] = b; s[ixj] = a; }
                }
            }
            __syncthreads();
        }
}

__global__ void k_surprise(const float* __restrict__ h) {
    int row = blockIdx.x, t = threadIdx.x;
    const float4* p = (const float4*)(h + (size_t)row * HD);
    float4 v = p[t];
    float s = v.x * v.x + v.y * v.y + v.z * v.z + v.w * v.w;
    #pragma unroll
    for (int o = 16; o; o >>= 1) s += __shfl_xor_sync(0xffffffffu, s, o);
    __shared__ float ws[8];
    if ((t & 31) == 0) ws[t >> 5] = s;
    __syncthreads();
    if (t < 8) {
        float x = ws[t];
        #pragma unroll
        for (int o = 4; o; o >>= 1) x += __shfl_xor_sync(0xffu, x, o);
        if (t == 0) g_surp[row] = 2.0f * sqrtf(x);
    }
}

__global__ void k_sort_surprise() {
    __shared__ unsigned long long sm[BSROWS];
    int t = threadIdx.x;
    for (int i = t; i < BSROWS; i += 1024) sm[i] = pack_kv(-g_surp[i], (unsigned)i);
    __syncthreads();
    bitonic_sort(sm, BSROWS, t, 1024);
    for (int i = t; i < BSROWS; i += 1024) g_top_i[i] = (int)(unsigned)sm[i];
}

__global__ void k_sort_least(const float* __restrict__ imp, const float* __restrict__ noise) {
    extern __shared__ unsigned long long dsm[];
    int t = threadIdx.x;
    for (int i = t; i < MSLOTS; i += 1024)
        dsm[i] = pack_kv(imp[i] + noise[i] * 1e-6f, (unsigned)i);
    __syncthreads();
    bitonic_sort(dsm, MSLOTS, t, 1024);
    for (int i = t; i < MSLOTS; i += 1024) g_least[i] = (int)(unsigned)dsm[i];
}

__global__ void k_copybuf(const float* __restrict__ src) {
    const float4* s = (const float4*)src;
    float4* d = (float4*)g_buf;
    size_t n = (size_t)MSLOTS * HD / 4;
    for (size_t i = blockIdx.x * 256ull + threadIdx.x; i < n; i += (size_t)gridDim.x * 256)
        d[i] = s[i];
}

__global__ void k_scatter(const float* __restrict__ hidden) {
    int i = blockIdx.x;
    int cand = g_top_i[i];
    if (g_surp[cand] > 64.0f) {
        int slot = g_least[i];
        const float4* src = (const float4*)(hidden + (size_t)cand * HD);
        float4* dst = (float4*)(g_buf + (size_t)slot * HD);
        dst[threadIdx.x] = src[threadIdx.x];
    }
}

// fp32 [R,1024] -> split bf16 [R,2048]
__global__ void k_split1024(const float* __restrict__ in, __nv_bfloat16* __restrict__ out,
                            int total) {
    for (int e = blockIdx.x * 256 + threadIdx.x; e < total; e += gridDim.x * 256) {
        int r = e >> 10, k = e & 1023;
        __nv_bfloat16 h, l;
        split2(in[e], h, l);
        out[((size_t)r << 11) + k] = h;
        out[((size_t)r << 11) + 1024 + k] = l;
    }
}

// transpose + split: buf[8192,1024] -> bT[1024,16384]
__global__ void k_tsplit(const float* __restrict__ in, __nv_bfloat16* __restrict__ out) {
    __shared__ float tile[32][33];
    int bc = blockIdx.x * 32, br = blockIdx.y * 32;
    int tx = threadIdx.x, ty = threadIdx.y;   // 32x8
    #pragma unroll
    for (int i = 0; i < 32; i += 8)
        tile[ty + i][tx] = in[(size_t)(br + ty + i) * 1024 + bc + tx];
    __syncthreads();
    #pragma unroll
    for (int i = 0; i < 32; i += 8) {
        __nv_bfloat16 h, l;
        split2(tile[tx][ty + i], h, l);
        size_t o = (size_t)(bc + ty + i) * 16384 + br + tx;
        out[o] = h;
        out[o + 8192] = l;
    }
}

// softmax: scores fp32 -> unnormalized exp as split bf16 + 1/rowsum
__global__ void k_softmax() {
    int row = blockIdx.x, t = threadIdx.x;   // 256 threads
    const float* p = g_sc + (size_t)row * MSLOTS;
    __nv_bfloat16* a = g_attnsp + (size_t)row * (2 * MSLOTS);
    __shared__ float sred[8];
    __shared__ float sbc;

    float m = -3.4e38f;
    for (int i = 4 * t; i < MSLOTS; i += 1024) {
        float4 v = *(const float4*)(p + i);
        m = fmaxf(m, fmaxf(fmaxf(v.x, v.y), fmaxf(v.z, v.w)));
    }
    #pragma unroll
    for (int o = 16; o; o >>= 1) m = fmaxf(m, __shfl_xor_sync(0xffffffffu, m, o));
    if ((t & 31) == 0) sred[t >> 5] = m;
    __syncthreads();
    if (t < 8) {
        float x = sred[t];
        #pragma unroll
        for (int o = 4; o; o >>= 1) x = fmaxf(x, __shfl_xor_sync(0xffu, x, o));
        if (t == 0) sbc = x;
    }
    __syncthreads();
    m = sbc;
    __syncthreads();

    float sum = 0.0f;
    for (int i = 4 * t; i < MSLOTS; i += 1024) {
        float4 v = *(const float4*)(p + i);
        float e0 = expf(v.x - m), e1 = expf(v.y - m), e2 = expf(v.z - m), e3 = expf(v.w - m);
        sum += e0 + e1 + e2 + e3;
        __align__(8) __nv_bfloat16 h[4], l[4];
        split2(e0, h[0], l[0]); split2(e1, h[1], l[1]);
        split2(e2, h[2], l[2]); split2(e3, h[3], l[3]);
        *(uint2*)(a + i) = *(uint2*)h;
        *(uint2*)(a + MSLOTS + i) = *(uint2*)l;
    }
    #pragma unroll
    for (int o = 16; o; o >>= 1) sum += __shfl_xor_sync(0xffffffffu, sum, o);
    if ((t & 31) == 0) sred[t >> 5] = sum;
    __syncthreads();
    if (t == 0) {
        float x = 0.0f;
        #pragma unroll
        for (int w = 0; w < 8; w++) x += sred[w];
        g_rinv[row] = 1.0f / x;
    }
}

// ---------------- host launch ----------------
extern "C" void kernel_launch(void* const* d_in, const int* in_sizes, int n_in,
                              void* d_out, int out_size) {
    const float* hidden = (const float*)d_in[0];
    const float* membuf = (const float*)d_in[1];
    const float* imp    = (const float*)d_in[2];
    const float* Wq     = (const float*)d_in[3];
    const float* bq     = (const float*)d_in[4];
    const float* Wk     = (const float*)d_in[5];
    const float* bk     = (const float*)d_in[6];
    const float* noise  = (const float*)d_in[7];
    float* out = (float*)d_out;

    cudaFuncSetAttribute(k_sort_least, cudaFuncAttributeMaxDynamicSharedMemorySize, 65536);
    cudaFuncSetAttribute(gemm_sp, cudaFuncAttributeMaxDynamicSharedMemorySize, GSMEM_TOTAL);

    void *p_buf, *p_hsp, *p_wqsp, *p_wksp, *p_bufsp, *p_qsp, *p_mksp, *p_attn, *p_bT, *p_sc, *p_rinv;
    cudaGetSymbolAddress(&p_buf, g_buf);
    cudaGetSymbolAddress(&p_hsp, g_hsp);
    cudaGetSymbolAddress(&p_wqsp, g_wqsp);
    cudaGetSymbolAddress(&p_wksp, g_wksp);
    cudaGetSymbolAddress(&p_bufsp, g_bufsp);
    cudaGetSymbolAddress(&p_qsp, g_qsp);
    cudaGetSymbolAddress(&p_mksp, g_mksp);
    cudaGetSymbolAddress(&p_attn, g_attnsp);
    cudaGetSymbolAddress(&p_bT, g_bTsp);
    cudaGetSymbolAddress(&p_sc, g_sc);
    cudaGetSymbolAddress(&p_rinv, g_rinv);

    // 1. surprise + sorts + memory update
    k_surprise<<<BSROWS, 256>>>(hidden);
    k_sort_surprise<<<1, 1024>>>();
    k_sort_least<<<1, 1024, 65536>>>(imp, noise);
    k_copybuf<<<2048, 256>>>(membuf);
    k_scatter<<<BSROWS, 256>>>(hidden);

    // 2. split conversions
    k_split1024<<<2048, 256>>>(hidden, (__nv_bfloat16*)p_hsp, BSROWS * HD);
    k_split1024<<<1024, 256>>>(Wq, (__nv_bfloat16*)p_wqsp, HD * HD);
    k_split1024<<<1024, 256>>>(Wk, (__nv_bfloat16*)p_wksp, HD * HD);
    k_split1024<<<2048, 256>>>((const float*)p_buf, (__nv_bfloat16*)p_bufsp, MSLOTS * HD);
    k_tsplit<<<dim3(32, 256), dim3(32, 8)>>>((const float*)p_buf, (__nv_bfloat16*)p_bT);

    // 3. q = hidden @ Wq^T + bq  -> split bf16
    gemm_sp<<<dim3(HD / 256, BSROWS / 128), 256, GSMEM_TOTAL>>>(
        (const __nv_bfloat16*)p_hsp, (const __nv_bfloat16*)p_wqsp, 2 * HD, 2 * HD, HD,
        bq, nullptr, 1.0f, nullptr, (__nv_bfloat16*)p_qsp, 2 * HD);

    // 4. mk = buf @ Wk^T + bk -> split bf16
    gemm_sp<<<dim3(HD / 256, MSLOTS / 128), 256, GSMEM_TOTAL>>>(
        (const __nv_bfloat16*)p_bufsp, (const __nv_bfloat16*)p_wksp, 2 * HD, 2 * HD, HD,
        bk, nullptr, 1.0f, nullptr, (__nv_bfloat16*)p_mksp, 2 * HD);

    // 5. scores = q @ mk^T / 32 -> fp32
    gemm_sp<<<dim3(MSLOTS / 256, BSROWS / 128), 256, GSMEM_TOTAL>>>(
        (const __nv_bfloat16*)p_qsp, (const __nv_bfloat16*)p_mksp, 2 * HD, 2 * HD, HD,
        nullptr, nullptr, 0.03125f, (float*)p_sc, nullptr, MSLOTS);

    // 6. softmax -> unnormalized exp split bf16 + 1/rowsum
    k_softmax<<<BSROWS, 256>>>();

    // 7. retrieved = (exp @ buf) * rinv -> d_out fp32
    gemm_sp<<<dim3(HD / 256, BSROWS / 128), 256, GSMEM_TOTAL>>>(
        (const __nv_bfloat16*)p_attn, (const __nv_bfloat16*)p_bT, 2 * MSLOTS, 2 * MSLOTS, MSLOTS,
        nullptr, (const float*)p_rinv, 1.0f, out, nullptr, HD);
}

// round 7
// speedup vs baseline: 3.4697x; 1.6129x over previous
#include <cuda_runtime.h>
#include <cuda_fp16.h>
#include <math.h>
#include <stdint.h>

#define BSROWS 4096   // B*S
#define HD     1024
#define MSLOTS 8192

// ---------------- device scratch (no allocations allowed) ----------------
__device__ float g_buf[MSLOTS * HD];                      // updated memory (fp32)
__device__ float g_sc[(size_t)BSROWS * MSLOTS];           // scores fp32 (128 MB)
__device__ __half g_hsp [BSROWS * 2 * HD];                // hidden split  [4096,2048]
__device__ __half g_wqsp[HD * 2 * HD];                    // Wq split
__device__ __half g_wksp[HD * 2 * HD];                    // Wk split
__device__ __half g_bufsp[MSLOTS * 2 * HD];               // buf split     [8192,2048]
__device__ __half g_qsp [BSROWS * 2 * HD];                // q split       [4096,2048]
__device__ __half g_mksp[MSLOTS * HD];                    // mk HI ONLY    [8192,1024]
__device__ __half g_attnsp[(size_t)BSROWS * 2 * MSLOTS];  // probs split [4096,16384]
__device__ __half g_bTsp[HD * MSLOTS];                    // buf^T HI ONLY [1024,8192]
__device__ float g_surp[BSROWS];
__device__ int   g_top_i[BSROWS];
__device__ int   g_least[MSLOTS];
__device__ float g_rinv[BSROWS];

// ---------------- PTX helpers (base sm_103 ISA only) ----------------
__device__ __forceinline__ uint32_t smem_u32(const void* p) {
    uint32_t a;
    asm("{ .reg .u64 t; cvta.to.shared.u64 t, %1; cvt.u32.u64 %0, t; }" : "=r"(a) : "l"(p));
    return a;
}
#define SWZ128(x) ((x) ^ (((x) >> 3) & 0x70))
__device__ __forceinline__ void cpasync16(uint32_t dst, const void* src) {
    asm volatile("cp.async.cg.shared.global [%0], [%1], 16;"
                 :: "r"(dst), "l"(__cvta_generic_to_global(src)) : "memory");
}
__device__ __forceinline__ void cp_commit() {
    asm volatile("cp.async.commit_group;" ::: "memory");
}
__device__ __forceinline__ void cp_wait1() {
    asm volatile("cp.async.wait_group 1;" ::: "memory");
}
__device__ __forceinline__ void ldsm4(uint32_t& r0, uint32_t& r1, uint32_t& r2, uint32_t& r3,
                                      uint32_t addr) {
    asm volatile("ldmatrix.sync.aligned.m8n8.x4.shared.b16 {%0,%1,%2,%3}, [%4];"
                 : "=r"(r0), "=r"(r1), "=r"(r2), "=r"(r3) : "r"(addr));
}
__device__ __forceinline__ void mma16816(float* c, const uint32_t* a, const uint32_t* b) {
    asm volatile(
        "mma.sync.aligned.m16n8k16.row.col.f32.f16.f16.f32 "
        "{%0,%1,%2,%3}, {%4,%5,%6,%7}, {%8,%9}, {%0,%1,%2,%3};"
        : "+f"(c[0]), "+f"(c[1]), "+f"(c[2]), "+f"(c[3])
        : "r"(a[0]), "r"(a[1]), "r"(a[2]), "r"(a[3]), "r"(b[0]), "r"(b[1]));
}
__device__ __forceinline__ void split2h(float v, __half& h, __half& l) {
    h = __float2half_rn(v);
    l = __float2half_rn(v - __half2float(h));
}

// ---------------- fp16 split GEMM: C[M,N] = A (x) B^T ----------------
// Tile 128M x 256N, BK=64, 2 stages, 128B swizzled rows (no padding).
// NSEG=3: passes (Ah,Bh),(Al,Bh),(Ah,Bl)  [full precision, ~2^-22]
// NSEG=2: passes (Ah,Bh),(Al,Bh)          [B effectively fp16, ~2^-12]
// A layout: hi at cols [0,Kseg), lo at [Kseg,2Kseg). B same when NSEG=3.
template<int NSEG>
__global__ void __launch_bounds__(256, 1)
gemm_h(const __half* __restrict__ A, const __half* __restrict__ B,
       int ldA, int ldB, int Kseg,
       const float* __restrict__ bias, const float* __restrict__ rowscale, float alpha,
       float* __restrict__ outF, __half* __restrict__ outS, int ldOut, int loOff)
{
    constexpr int STB = 32768 + 32768 * (NSEG - 1);   // 2seg:64K  3seg:96K
    extern __shared__ char smem[];
    const uint32_t sb = smem_u32(smem);
    const int tid = threadIdx.x;
    const int wid = tid >> 5;
    const int lane = tid & 31;
    const int wm = wid & 1;      // 2 warps over M (64 rows)
    const int wn = wid >> 1;     // 4 warps over N (64 cols)
    const int row0 = blockIdx.y * 128;
    const int col0 = blockIdx.x * 256;
    const int C = Kseg >> 6;     // 64-wide k-chunks

    auto load_chunk = [&](int c) {
        const uint32_t st = sb + (c & 1) * STB;
        const int kcol = c << 6;
        #pragma unroll
        for (int i = 0; i < 4; i++) {            // A: 1024 16B units
            int u = tid + (i << 8);
            int r = u >> 3, uc = u & 7;
            uint32_t so = SWZ128(r * 128 + uc * 16);
            const __half* g = A + (size_t)(row0 + r) * ldA + kcol + uc * 8;
            cpasync16(st + so, g);                     // Ah
            cpasync16(st + 16384 + so, g + Kseg);      // Al
        }
        #pragma unroll
        for (int i = 0; i < 8; i++) {            // B: 2048 16B units
            int u = tid + (i << 8);
            int r = u >> 3, uc = u & 7;
            uint32_t so = SWZ128(r * 128 + uc * 16);
            const __half* g = B + (size_t)(col0 + r) * ldB + kcol + uc * 8;
            cpasync16(st + 32768 + so, g);             // Bh
            if (NSEG == 3) cpasync16(st + 65536 + so, g + Kseg);  // Bl
        }
    };

    float acc[4][8][4];
    #pragma unroll
    for (int mt = 0; mt < 4; mt++)
        #pragma unroll
        for (int nt = 0; nt < 8; nt++)
            #pragma unroll
            for (int i = 0; i < 4; i++) acc[mt][nt][i] = 0.0f;

    load_chunk(0); cp_commit();
    if (C > 1) load_chunk(1);
    cp_commit();

    for (int c = 0; c < C; c++) {
        cp_wait1();
        __syncthreads();
        const uint32_t stg = sb + (c & 1) * STB;
        #pragma unroll
        for (int p = 0; p < NSEG; p++) {
            const uint32_t aB = stg + ((p == 1) ? 16384 : 0);
            const uint32_t bB = stg + ((NSEG == 3 && p == 2) ? 65536 : 32768);
            #pragma unroll
            for (int ks = 0; ks < 4; ks++) {
                uint32_t af[4][4], bf[8][2];
                #pragma unroll
                for (int mt = 0; mt < 4; mt++) {
                    int row = wm * 64 + mt * 16 + (lane & 15);
                    int colb = (ks * 16 + ((lane >> 4) << 3)) * 2;
                    ldsm4(af[mt][0], af[mt][1], af[mt][2], af[mt][3],
                          aB + SWZ128(row * 128 + colb));
                }
                #pragma unroll
                for (int nt2 = 0; nt2 < 4; nt2++) {
                    int row = wn * 64 + nt2 * 16 + ((lane >> 4) << 3) + (lane & 7);
                    int colb = (ks * 16 + (((lane >> 3) & 1) << 3)) * 2;
                    ldsm4(bf[nt2*2][0], bf[nt2*2][1], bf[nt2*2+1][0], bf[nt2*2+1][1],
                          bB + SWZ128(row * 128 + colb));
                }
                #pragma unroll
                for (int mt = 0; mt < 4; mt++)
                    #pragma unroll
                    for (int nt = 0; nt < 8; nt++)
                        mma16816(acc[mt][nt], af[mt], bf[nt]);
            }
        }
        __syncthreads();
        if (c + 2 < C) load_chunk(c + 2);
        cp_commit();                 // unconditional: keeps wait_group exact in tail
    }

    // ---- epilogue ----
    #pragma unroll
    for (int mt = 0; mt < 4; mt++) {
        const int r0g = row0 + wm * 64 + mt * 16 + (lane >> 2);
        #pragma unroll
        for (int half = 0; half < 2; half++) {
            const int rg = r0g + half * 8;
            const float rs = rowscale ? rowscale[rg] : 1.0f;
            #pragma unroll
            for (int nt = 0; nt < 8; nt++) {
                const int cg = col0 + wn * 64 + nt * 8 + ((lane & 3) << 1);
                float v0 = acc[mt][nt][half * 2 + 0] * alpha;
                float v1 = acc[mt][nt][half * 2 + 1] * alpha;
                if (bias) { v0 += bias[cg]; v1 += bias[cg + 1]; }
                v0 *= rs; v1 *= rs;
                if (outF) {
                    *(float2*)(outF + (size_t)rg * ldOut + cg) = make_float2(v0, v1);
                } else {
                    __half h0, l0, h1, l1;
                    split2h(v0, h0, l0); split2h(v1, h1, l1);
                    __half2 hp; hp.x = h0; hp.y = h1;
                    *(__half2*)(outS + (size_t)rg * ldOut + cg) = hp;
                    if (loOff) {
                        __half2 lp; lp.x = l0; lp.y = l1;
                        *(__half2*)(outS + (size_t)rg * ldOut + loOff + cg) = lp;
                    }
                }
            }
        }
    }
}

// ---------------- pre/post kernels ----------------
__device__ __forceinline__ unsigned long long pack_kv(float key, unsigned idx) {
    unsigned u = __float_as_uint(key);
    u = (u & 0x80000000u) ? ~u : (u | 0x80000000u);
    return ((unsigned long long)u << 32) | idx;
}
__device__ __forceinline__ void bitonic_sort(unsigned long long* s, int n, int t, int nt) {
    for (int k = 2; k <= n; k <<= 1)
        for (int j = k >> 1; j > 0; j >>= 1) {
            for (int i = t; i < n; i += nt) {
                int ixj = i ^ j;
                if (ixj > i) {
                    unsigned long long a = s[i], b = s[ixj];
                    bool up = ((i & k) == 0);
                    if ((a > b) == up) { s[i] = b; s[ixj] = a; }
                }
            }
            __syncthreads();
        }
}

__global__ void k_surprise(const float* __restrict__ h) {
    int row = blockIdx.x, t = threadIdx.x;
    const float4* p = (const float4*)(h + (size_t)row * HD);
    float4 v = p[t];
    float s = v.x * v.x + v.y * v.y + v.z * v.z + v.w * v.w;
    #pragma unroll
    for (int o = 16; o; o >>= 1) s += __shfl_xor_sync(0xffffffffu, s, o);
    __shared__ float ws[8];
    if ((t & 31) == 0) ws[t >> 5] = s;
    __syncthreads();
    if (t < 8) {
        float x = ws[t];
        #pragma unroll
        for (int o = 4; o; o >>= 1) x += __shfl_xor_sync(0xffu, x, o);
        if (t == 0) g_surp[row] = 2.0f * sqrtf(x);
    }
}

__global__ void k_sort_surprise() {
    __shared__ unsigned long long sm[BSROWS];
    int t = threadIdx.x;
    for (int i = t; i < BSROWS; i += 1024) sm[i] = pack_kv(-g_surp[i], (unsigned)i);
    __syncthreads();
    bitonic_sort(sm, BSROWS, t, 1024);
    for (int i = t; i < BSROWS; i += 1024) g_top_i[i] = (int)(unsigned)sm[i];
}

__global__ void k_sort_least(const float* __restrict__ imp, const float* __restrict__ noise) {
    extern __shared__ unsigned long long dsm[];
    int t = threadIdx.x;
    for (int i = t; i < MSLOTS; i += 1024)
        dsm[i] = pack_kv(imp[i] + noise[i] * 1e-6f, (unsigned)i);
    __syncthreads();
    bitonic_sort(dsm, MSLOTS, t, 1024);
    for (int i = t; i < MSLOTS; i += 1024) g_least[i] = (int)(unsigned)dsm[i];
}

__global__ void k_copybuf(const float* __restrict__ src) {
    const float4* s = (const float4*)src;
    float4* d = (float4*)g_buf;
    size_t n = (size_t)MSLOTS * HD / 4;
    for (size_t i = blockIdx.x * 256ull + threadIdx.x; i < n; i += (size_t)gridDim.x * 256)
        d[i] = s[i];
}

__global__ void k_scatter(const float* __restrict__ hidden) {
    int i = blockIdx.x;
    int cand = g_top_i[i];
    if (g_surp[cand] > 64.0f) {
        int slot = g_least[i];
        const float4* src = (const float4*)(hidden + (size_t)cand * HD);
        float4* dst = (float4*)(g_buf + (size_t)slot * HD);
        dst[threadIdx.x] = src[threadIdx.x];
    }
}

// fp32 [R,1024] -> split fp16 [R,2048]
__global__ void k_split1024(const float* __restrict__ in, __half* __restrict__ out,
                            int total) {
    for (int e = blockIdx.x * 256 + threadIdx.x; e < total; e += gridDim.x * 256) {
        int r = e >> 10, k = e & 1023;
        __half h, l;
        split2h(in[e], h, l);
        out[((size_t)r << 11) + k] = h;
        out[((size_t)r << 11) + 1024 + k] = l;
    }
}

// transpose: buf[8192,1024] -> bT HI ONLY [1024,8192]
__global__ void k_tsplit(const float* __restrict__ in, __half* __restrict__ out) {
    __shared__ float tile[32][33];
    int bc = blockIdx.x * 32, br = blockIdx.y * 32;
    int tx = threadIdx.x, ty = threadIdx.y;   // 32x8
    #pragma unroll
    for (int i = 0; i < 32; i += 8)
        tile[ty + i][tx] = in[(size_t)(br + ty + i) * 1024 + bc + tx];
    __syncthreads();
    #pragma unroll
    for (int i = 0; i < 32; i += 8)
        out[(size_t)(bc + ty + i) * MSLOTS + br + tx] = __float2half_rn(tile[tx][ty + i]);
}

// softmax: scores fp32 -> unnormalized exp as split fp16 + 1/rowsum
__global__ void k_softmax() {
    int row = blockIdx.x, t = threadIdx.x;   // 256 threads
    const float* p = g_sc + (size_t)row * MSLOTS;
    __half* a = g_attnsp + (size_t)row * (2 * MSLOTS);
    __shared__ float sred[8];
    __shared__ float sbc;

    float m = -3.4e38f;
    for (int i = 4 * t; i < MSLOTS; i += 1024) {
        float4 v = *(const float4*)(p + i);
        m = fmaxf(m, fmaxf(fmaxf(v.x, v.y), fmaxf(v.z, v.w)));
    }
    #pragma unroll
    for (int o = 16; o; o >>= 1) m = fmaxf(m, __shfl_xor_sync(0xffffffffu, m, o));
    if ((t & 31) == 0) sred[t >> 5] = m;
    __syncthreads();
    if (t < 8) {
        float x = sred[t];
        #pragma unroll
        for (int o = 4; o; o >>= 1) x = fmaxf(x, __shfl_xor_sync(0xffu, x, o));
        if (t == 0) sbc = x;
    }
    __syncthreads();
    m = sbc;
    __syncthreads();

    float sum = 0.0f;
    for (int i = 4 * t; i < MSLOTS; i += 1024) {
        float4 v = *(const float4*)(p + i);
        float e0 = expf(v.x - m), e1 = expf(v.y - m), e2 = expf(v.z - m), e3 = expf(v.w - m);
        sum += e0 + e1 + e2 + e3;
        __align__(8) __half h[4], l[4];
        split2h(e0, h[0], l[0]); split2h(e1, h[1], l[1]);
        split2h(e2, h[2], l[2]); split2h(e3, h[3], l[3]);
        *(uint2*)(a + i) = *(uint2*)h;
        *(uint2*)(a + MSLOTS + i) = *(uint2*)l;
    }
    #pragma unroll
    for (int o = 16; o; o >>= 1) sum += __shfl_xor_sync(0xffffffffu, sum, o);
    if ((t & 31) == 0) sred[t >> 5] = sum;
    __syncthreads();
    if (t == 0) {
        float x = 0.0f;
        #pragma unroll
        for (int w = 0; w < 8; w++) x += sred[w];
        g_rinv[row] = 1.0f / x;
    }
}

// ---------------- host launch ----------------
extern "C" void kernel_launch(void* const* d_in, const int* in_sizes, int n_in,
                              void* d_out, int out_size) {
    const float* hidden = (const float*)d_in[0];
    const float* membuf = (const float*)d_in[1];
    const float* imp    = (const float*)d_in[2];
    const float* Wq     = (const float*)d_in[3];
    const float* bq     = (const float*)d_in[4];
    const float* Wk     = (const float*)d_in[5];
    const float* bk     = (const float*)d_in[6];
    const float* noise  = (const float*)d_in[7];
    float* out = (float*)d_out;

    cudaFuncSetAttribute(k_sort_least, cudaFuncAttributeMaxDynamicSharedMemorySize, 65536);
    cudaFuncSetAttribute(gemm_h<2>, cudaFuncAttributeMaxDynamicSharedMemorySize, 2 * 65536);
    cudaFuncSetAttribute(gemm_h<3>, cudaFuncAttributeMaxDynamicSharedMemorySize, 2 * 98304);

    void *p_buf, *p_hsp, *p_wqsp, *p_wksp, *p_bufsp, *p_qsp, *p_mksp, *p_attn, *p_bT, *p_sc, *p_rinv;
    cudaGetSymbolAddress(&p_buf, g_buf);
    cudaGetSymbolAddress(&p_hsp, g_hsp);
    cudaGetSymbolAddress(&p_wqsp, g_wqsp);
    cudaGetSymbolAddress(&p_wksp, g_wksp);
    cudaGetSymbolAddress(&p_bufsp, g_bufsp);
    cudaGetSymbolAddress(&p_qsp, g_qsp);
    cudaGetSymbolAddress(&p_mksp, g_mksp);
    cudaGetSymbolAddress(&p_attn, g_attnsp);
    cudaGetSymbolAddress(&p_bT, g_bTsp);
    cudaGetSymbolAddress(&p_sc, g_sc);
    cudaGetSymbolAddress(&p_rinv, g_rinv);

    // 1. surprise + sorts + memory update
    k_surprise<<<BSROWS, 256>>>(hidden);
    k_sort_surprise<<<1, 1024>>>();
    k_sort_least<<<1, 1024, 65536>>>(imp, noise);
    k_copybuf<<<2048, 256>>>(membuf);
    k_scatter<<<BSROWS, 256>>>(hidden);

    // 2. split conversions (fp16)
    k_split1024<<<2048, 256>>>(hidden, (__half*)p_hsp, BSROWS * HD);
    k_split1024<<<1024, 256>>>(Wq, (__half*)p_wqsp, HD * HD);
    k_split1024<<<1024, 256>>>(Wk, (__half*)p_wksp, HD * HD);
    k_split1024<<<2048, 256>>>((const float*)p_buf, (__half*)p_bufsp, MSLOTS * HD);
    k_tsplit<<<dim3(32, 256), dim3(32, 8)>>>((const float*)p_buf, (__half*)p_bT);

    // 3. q = hidden @ Wq^T + bq -> split fp16 (3-seg: full precision)
    gemm_h<3><<<dim3(HD / 256, BSROWS / 128), 256, 2 * 98304>>>(
        (const __half*)p_hsp, (const __half*)p_wqsp, 2 * HD, 2 * HD, HD,
        bq, nullptr, 1.0f, nullptr, (__half*)p_qsp, 2 * HD, HD);

    // 4. mk = buf @ Wk^T + bk -> fp16 HI ONLY (3-seg)
    gemm_h<3><<<dim3(HD / 256, MSLOTS / 128), 256, 2 * 98304>>>(
        (const __half*)p_bufsp, (const __half*)p_wksp, 2 * HD, 2 * HD, HD,
        bk, nullptr, 1.0f, nullptr, (__half*)p_mksp, HD, 0);

    // 5. scores = q @ mk^T / 32 -> fp32 (2-seg: q split x mk hi)
    gemm_h<2><<<dim3(MSLOTS / 256, BSROWS / 128), 256, 2 * 65536>>>(
        (const __half*)p_qsp, (const __half*)p_mksp, 2 * HD, HD, HD,
        nullptr, nullptr, 0.03125f, (float*)p_sc, nullptr, MSLOTS, 0);

    // 6. softmax -> unnormalized exp split fp16 + 1/rowsum
    k_softmax<<<BSROWS, 256>>>();

    // 7. retrieved = (exp @ buf) * rinv -> d_out fp32 (2-seg: probs split x bT hi)
    gemm_h<2><<<dim3(HD / 256, BSROWS / 128), 256, 2 * 65536>>>(
        (const __half*)p_attn, (const __half*)p_bT, 2 * MSLOTS, MSLOTS, MSLOTS,
        nullptr, (const float*)p_rinv, 1.0f, out, nullptr, HD, 0);
}

// round 8
// speedup vs baseline: 3.8247x; 1.1023x over previous
#include <cuda_runtime.h>
#include <cuda_fp16.h>
#include <math.h>
#include <stdint.h>

#define BSROWS 4096   // B*S
#define HD     1024
#define MSLOTS 8192

// ---------------- device scratch (no allocations allowed) ----------------
__device__ float g_buf[MSLOTS * HD];                      // updated memory (fp32)
__device__ float g_sc[(size_t)BSROWS * MSLOTS];           // scores fp32 (128 MB)
__device__ __half g_hsp [BSROWS * 2 * HD];                // hidden split  [4096,2048]
__device__ __half g_wqsp[HD * 2 * HD];                    // Wq split
__device__ __half g_wksp[HD * 2 * HD];                    // Wk split
__device__ __half g_bufsp[MSLOTS * 2 * HD];               // buf split     [8192,2048]
__device__ __half g_qsp [BSROWS * 2 * HD];                // q split       [4096,2048]
__device__ __half g_mksp[MSLOTS * HD];                    // mk HI ONLY    [8192,1024]
__device__ __half g_attnsp[(size_t)BSROWS * 2 * MSLOTS];  // probs split [4096,16384]
__device__ __half g_bTsp[HD * MSLOTS];                    // buf^T HI ONLY [1024,8192]
__device__ float g_surp[BSROWS];
__device__ int   g_top_i[BSROWS];
__device__ int   g_least[MSLOTS];
__device__ float g_rinv[BSROWS];

// ---------------- PTX helpers (base sm_103 ISA only) ----------------
__device__ __forceinline__ uint32_t smem_u32(const void* p) {
    uint32_t a;
    asm("{ .reg .u64 t; cvta.to.shared.u64 t, %1; cvt.u32.u64 %0, t; }" : "=r"(a) : "l"(p));
    return a;
}
#define SWZ128(x) ((x) ^ (((x) >> 3) & 0x70))
__device__ __forceinline__ void cpasync16(uint32_t dst, const void* src) {
    asm volatile("cp.async.cg.shared.global [%0], [%1], 16;"
                 :: "r"(dst), "l"(__cvta_generic_to_global(src)) : "memory");
}
__device__ __forceinline__ void cp_commit() {
    asm volatile("cp.async.commit_group;" ::: "memory");
}
__device__ __forceinline__ void cp_wait1() {
    asm volatile("cp.async.wait_group 1;" ::: "memory");
}
__device__ __forceinline__ void ldsm4(uint32_t& r0, uint32_t& r1, uint32_t& r2, uint32_t& r3,
                                      uint32_t addr) {
    asm volatile("ldmatrix.sync.aligned.m8n8.x4.shared.b16 {%0,%1,%2,%3}, [%4];"
                 : "=r"(r0), "=r"(r1), "=r"(r2), "=r"(r3) : "r"(addr));
}
__device__ __forceinline__ void mma16816(float* c, const uint32_t* a, const uint32_t* b) {
    asm volatile(
        "mma.sync.aligned.m16n8k16.row.col.f32.f16.f16.f32 "
        "{%0,%1,%2,%3}, {%4,%5,%6,%7}, {%8,%9}, {%0,%1,%2,%3};"
        : "+f"(c[0]), "+f"(c[1]), "+f"(c[2]), "+f"(c[3])
        : "r"(a[0]), "r"(a[1]), "r"(a[2]), "r"(a[3]), "r"(b[0]), "r"(b[1]));
}
__device__ __forceinline__ void split2h(float v, __half& h, __half& l) {
    h = __float2half_rn(v);
    l = __float2half_rn(v - __half2float(h));
}

// ---------------- fp16 split GEMM: C[M,N] = A (x) B^T ----------------
// Tile 128M x 256N, BK=64, 2 stages, 128B swizzled rows.
// Fragment loads hoisted across passes: each k16-step loads af_h/af_l/bf_h
// (and bf_l for NSEG=3) ONCE, then issues all passes' MMAs from registers.
// NSEG=3: (Ah,Bh)+(Al,Bh)+(Ah,Bl)   NSEG=2: (Ah,Bh)+(Al,Bh)
template<int NSEG>
__global__ void __launch_bounds__(256, 1)
gemm_h(const __half* __restrict__ A, const __half* __restrict__ B,
       int ldA, int ldB, int Kseg,
       const float* __restrict__ bias, const float* __restrict__ rowscale, float alpha,
       float* __restrict__ outF, __half* __restrict__ outS, int ldOut, int loOff)
{
    constexpr int STB = 32768 + 32768 * (NSEG - 1);   // 2seg:64K  3seg:96K
    extern __shared__ char smem[];
    const uint32_t sb = smem_u32(smem);
    const int tid = threadIdx.x;
    const int wid = tid >> 5;
    const int lane = tid & 31;
    const int wm = wid & 1;      // 2 warps over M (64 rows)
    const int wn = wid >> 1;     // 4 warps over N (64 cols)
    const int row0 = blockIdx.y * 128;
    const int col0 = blockIdx.x * 256;
    const int C = Kseg >> 6;     // 64-wide k-chunks

    auto load_chunk = [&](int c) {
        const uint32_t st = sb + (c & 1) * STB;
        const int kcol = c << 6;
        #pragma unroll
        for (int i = 0; i < 4; i++) {            // A: 1024 16B units
            int u = tid + (i << 8);
            int r = u >> 3, uc = u & 7;
            uint32_t so = SWZ128(r * 128 + uc * 16);
            const __half* g = A + (size_t)(row0 + r) * ldA + kcol + uc * 8;
            cpasync16(st + so, g);                     // Ah
            cpasync16(st + 16384 + so, g + Kseg);      // Al
        }
        #pragma unroll
        for (int i = 0; i < 8; i++) {            // B: 2048 16B units
            int u = tid + (i << 8);
            int r = u >> 3, uc = u & 7;
            uint32_t so = SWZ128(r * 128 + uc * 16);
            const __half* g = B + (size_t)(col0 + r) * ldB + kcol + uc * 8;
            cpasync16(st + 32768 + so, g);             // Bh
            if (NSEG == 3) cpasync16(st + 65536 + so, g + Kseg);  // Bl
        }
    };

    float acc[4][8][4];
    #pragma unroll
    for (int mt = 0; mt < 4; mt++)
        #pragma unroll
        for (int nt = 0; nt < 8; nt++)
            #pragma unroll
            for (int i = 0; i < 4; i++) acc[mt][nt][i] = 0.0f;

    load_chunk(0); cp_commit();
    if (C > 1) load_chunk(1);
    cp_commit();

    for (int c = 0; c < C; c++) {
        cp_wait1();
        __syncthreads();
        const uint32_t stg = sb + (c & 1) * STB;
        #pragma unroll
        for (int ks = 0; ks < 4; ks++) {
            // ---- hoisted fragment loads (once per k16-step) ----
            uint32_t ah[4][4], al[4][4], bh[8][2], bl[8][2];
            #pragma unroll
            for (int mt = 0; mt < 4; mt++) {
                int row = wm * 64 + mt * 16 + (lane & 15);
                int colb = (ks * 16 + ((lane >> 4) << 3)) * 2;
                uint32_t so = SWZ128(row * 128 + colb);
                ldsm4(ah[mt][0], ah[mt][1], ah[mt][2], ah[mt][3], stg + so);
                ldsm4(al[mt][0], al[mt][1], al[mt][2], al[mt][3], stg + 16384 + so);
            }
            #pragma unroll
            for (int nt2 = 0; nt2 < 4; nt2++) {
                int row = wn * 64 + nt2 * 16 + ((lane >> 4) << 3) + (lane & 7);
                int colb = (ks * 16 + (((lane >> 3) & 1) << 3)) * 2;
                uint32_t so = SWZ128(row * 128 + colb);
                ldsm4(bh[nt2*2][0], bh[nt2*2][1], bh[nt2*2+1][0], bh[nt2*2+1][1],
                      stg + 32768 + so);
                if (NSEG == 3)
                    ldsm4(bl[nt2*2][0], bl[nt2*2][1], bl[nt2*2+1][0], bl[nt2*2+1][1],
                          stg + 65536 + so);
            }
            // ---- all passes from registers ----
            #pragma unroll
            for (int mt = 0; mt < 4; mt++)
                #pragma unroll
                for (int nt = 0; nt < 8; nt++)
                    mma16816(acc[mt][nt], ah[mt], bh[nt]);
            #pragma unroll
            for (int mt = 0; mt < 4; mt++)
                #pragma unroll
                for (int nt = 0; nt < 8; nt++)
                    mma16816(acc[mt][nt], al[mt], bh[nt]);
            if (NSEG == 3) {
                #pragma unroll
                for (int mt = 0; mt < 4; mt++)
                    #pragma unroll
                    for (int nt = 0; nt < 8; nt++)
                        mma16816(acc[mt][nt], ah[mt], bl[nt]);
            }
        }
        __syncthreads();
        if (c + 2 < C) load_chunk(c + 2);
        cp_commit();                 // unconditional: keeps wait_group exact in tail
    }

    // ---- epilogue ----
    #pragma unroll
    for (int mt = 0; mt < 4; mt++) {
        const int r0g = row0 + wm * 64 + mt * 16 + (lane >> 2);
        #pragma unroll
        for (int half = 0; half < 2; half++) {
            const int rg = r0g + half * 8;
            const float rs = rowscale ? rowscale[rg] : 1.0f;
            #pragma unroll
            for (int nt = 0; nt < 8; nt++) {
                const int cg = col0 + wn * 64 + nt * 8 + ((lane & 3) << 1);
                float v0 = acc[mt][nt][half * 2 + 0] * alpha;
                float v1 = acc[mt][nt][half * 2 + 1] * alpha;
                if (bias) { v0 += bias[cg]; v1 += bias[cg + 1]; }
                v0 *= rs; v1 *= rs;
                if (outF) {
                    *(float2*)(outF + (size_t)rg * ldOut + cg) = make_float2(v0, v1);
                } else {
                    __half h0, l0, h1, l1;
                    split2h(v0, h0, l0); split2h(v1, h1, l1);
                    __half2 hp; hp.x = h0; hp.y = h1;
                    *(__half2*)(outS + (size_t)rg * ldOut + cg) = hp;
                    if (loOff) {
                        __half2 lp; lp.x = l0; lp.y = l1;
                        *(__half2*)(outS + (size_t)rg * ldOut + loOff + cg) = lp;
                    }
                }
            }
        }
    }
}

// ---------------- pre/post kernels ----------------
__device__ __forceinline__ unsigned long long pack_kv(float key, unsigned idx) {
    unsigned u = __float_as_uint(key);
    u = (u & 0x80000000u) ? ~u : (u | 0x80000000u);
    return ((unsigned long long)u << 32) | idx;
}
__device__ __forceinline__ void bitonic_sort(unsigned long long* s, int n, int t, int nt) {
    for (int k = 2; k <= n; k <<= 1)
        for (int j = k >> 1; j > 0; j >>= 1) {
            for (int i = t; i < n; i += nt) {
                int ixj = i ^ j;
                if (ixj > i) {
                    unsigned long long a = s[i], b = s[ixj];
                    bool up = ((i & k) == 0);
                    if ((a > b) == up) { s[i] = b; s[ixj] = a; }
                }
            }
            __syncthreads();
        }
}

__global__ void k_surprise(const float* __restrict__ h) {
    int row = blockIdx.x, t = threadIdx.x;
    const float4* p = (const float4*)(h + (size_t)row * HD);
    float4 v = p[t];
    float s = v.x * v.x + v.y * v.y + v.z * v.z + v.w * v.w;
    #pragma unroll
    for (int o = 16; o; o >>= 1) s += __shfl_xor_sync(0xffffffffu, s, o);
    __shared__ float ws[8];
    if ((t & 31) == 0) ws[t >> 5] = s;
    __syncthreads();
    if (t < 8) {
        float x = ws[t];
        #pragma unroll
        for (int o = 4; o; o >>= 1) x += __shfl_xor_sync(0xffu, x, o);
        if (t == 0) g_surp[row] = 2.0f * sqrtf(x);
    }
}

__global__ void k_sort_surprise() {
    __shared__ unsigned long long sm[BSROWS];
    int t = threadIdx.x;
    for (int i = t; i < BSROWS; i += 1024) sm[i] = pack_kv(-g_surp[i], (unsigned)i);
    __syncthreads();
    bitonic_sort(sm, BSROWS, t, 1024);
    for (int i = t; i < BSROWS; i += 1024) g_top_i[i] = (int)(unsigned)sm[i];
}

__global__ void k_sort_least(const float* __restrict__ imp, const float* __restrict__ noise) {
    extern __shared__ unsigned long long dsm[];
    int t = threadIdx.x;
    for (int i = t; i < MSLOTS; i += 1024)
        dsm[i] = pack_kv(imp[i] + noise[i] * 1e-6f, (unsigned)i);
    __syncthreads();
    bitonic_sort(dsm, MSLOTS, t, 1024);
    for (int i = t; i < MSLOTS; i += 1024) g_least[i] = (int)(unsigned)dsm[i];
}

__global__ void k_copybuf(const float* __restrict__ src) {
    const float4* s = (const float4*)src;
    float4* d = (float4*)g_buf;
    size_t n = (size_t)MSLOTS * HD / 4;
    for (size_t i = blockIdx.x * 256ull + threadIdx.x; i < n; i += (size_t)gridDim.x * 256)
        d[i] = s[i];
}

__global__ void k_scatter(const float* __restrict__ hidden) {
    int i = blockIdx.x;
    int cand = g_top_i[i];
    if (g_surp[cand] > 64.0f) {
        int slot = g_least[i];
        const float4* src = (const float4*)(hidden + (size_t)cand * HD);
        float4* dst = (float4*)(g_buf + (size_t)slot * HD);
        dst[threadIdx.x] = src[threadIdx.x];
    }
}

// fp32 [R,1024] -> split fp16 [R,2048]
__global__ void k_split1024(const float* __restrict__ in, __half* __restrict__ out,
                            int total) {
    for (int e = blockIdx.x * 256 + threadIdx.x; e < total; e += gridDim.x * 256) {
        int r = e >> 10, k = e & 1023;
        __half h, l;
        split2h(in[e], h, l);
        out[((size_t)r << 11) + k] = h;
        out[((size_t)r << 11) + 1024 + k] = l;
    }
}

// transpose: buf[8192,1024] -> bT HI ONLY [1024,8192]
__global__ void k_tsplit(const float* __restrict__ in, __half* __restrict__ out) {
    __shared__ float tile[32][33];
    int bc = blockIdx.x * 32, br = blockIdx.y * 32;
    int tx = threadIdx.x, ty = threadIdx.y;   // 32x8
    #pragma unroll
    for (int i = 0; i < 32; i += 8)
        tile[ty + i][tx] = in[(size_t)(br + ty + i) * 1024 + bc + tx];
    __syncthreads();
    #pragma unroll
    for (int i = 0; i < 32; i += 8)
        out[(size_t)(bc + ty + i) * MSLOTS + br + tx] = __float2half_rn(tile[tx][ty + i]);
}

// softmax: scores fp32 -> unnormalized exp as split fp16 + 1/rowsum
__global__ void k_softmax() {
    int row = blockIdx.x, t = threadIdx.x;   // 256 threads
    const float* p = g_sc + (size_t)row * MSLOTS;
    __half* a = g_attnsp + (size_t)row * (2 * MSLOTS);
    __shared__ float sred[8];
    __shared__ float sbc;

    float m = -3.4e38f;
    for (int i = 4 * t; i < MSLOTS; i += 1024) {
        float4 v = *(const float4*)(p + i);
        m = fmaxf(m, fmaxf(fmaxf(v.x, v.y), fmaxf(v.z, v.w)));
    }
    #pragma unroll
    for (int o = 16; o; o >>= 1) m = fmaxf(m, __shfl_xor_sync(0xffffffffu, m, o));
    if ((t & 31) == 0) sred[t >> 5] = m;
    __syncthreads();
    if (t < 8) {
        float x = sred[t];
        #pragma unroll
        for (int o = 4; o; o >>= 1) x = fmaxf(x, __shfl_xor_sync(0xffu, x, o));
        if (t == 0) sbc = x;
    }
    __syncthreads();
    m = sbc;
    __syncthreads();

    float sum = 0.0f;
    for (int i = 4 * t; i < MSLOTS; i += 1024) {
        float4 v = *(const float4*)(p + i);
        float e0 = expf(v.x - m), e1 = expf(v.y - m), e2 = expf(v.z - m), e3 = expf(v.w - m);
        sum += e0 + e1 + e2 + e3;
        __align__(8) __half h[4], l[4];
        split2h(e0, h[0], l[0]); split2h(e1, h[1], l[1]);
        split2h(e2, h[2], l[2]); split2h(e3, h[3], l[3]);
        *(uint2*)(a + i) = *(uint2*)h;
        *(uint2*)(a + MSLOTS + i) = *(uint2*)l;
    }
    #pragma unroll
    for (int o = 16; o; o >>= 1) sum += __shfl_xor_sync(0xffffffffu, sum, o);
    if ((t & 31) == 0) sred[t >> 5] = sum;
    __syncthreads();
    if (t == 0) {
        float x = 0.0f;
        #pragma unroll
        for (int w = 0; w < 8; w++) x += sred[w];
        g_rinv[row] = 1.0f / x;
    }
}

// ---------------- host launch ----------------
extern "C" void kernel_launch(void* const* d_in, const int* in_sizes, int n_in,
                              void* d_out, int out_size) {
    const float* hidden = (const float*)d_in[0];
    const float* membuf = (const float*)d_in[1];
    const float* imp    = (const float*)d_in[2];
    const float* Wq     = (const float*)d_in[3];
    const float* bq     = (const float*)d_in[4];
    const float* Wk     = (const float*)d_in[5];
    const float* bk     = (const float*)d_in[6];
    const float* noise  = (const float*)d_in[7];
    float* out = (float*)d_out;

    cudaFuncSetAttribute(k_sort_least, cudaFuncAttributeMaxDynamicSharedMemorySize, 65536);
    cudaFuncSetAttribute(gemm_h<2>, cudaFuncAttributeMaxDynamicSharedMemorySize, 2 * 65536);
    cudaFuncSetAttribute(gemm_h<3>, cudaFuncAttributeMaxDynamicSharedMemorySize, 2 * 98304);

    void *p_buf, *p_hsp, *p_wqsp, *p_wksp, *p_bufsp, *p_qsp, *p_mksp, *p_attn, *p_bT, *p_sc, *p_rinv;
    cudaGetSymbolAddress(&p_buf, g_buf);
    cudaGetSymbolAddress(&p_hsp, g_hsp);
    cudaGetSymbolAddress(&p_wqsp, g_wqsp);
    cudaGetSymbolAddress(&p_wksp, g_wksp);
    cudaGetSymbolAddress(&p_bufsp, g_bufsp);
    cudaGetSymbolAddress(&p_qsp, g_qsp);
    cudaGetSymbolAddress(&p_mksp, g_mksp);
    cudaGetSymbolAddress(&p_attn, g_attnsp);
    cudaGetSymbolAddress(&p_bT, g_bTsp);
    cudaGetSymbolAddress(&p_sc, g_sc);
    cudaGetSymbolAddress(&p_rinv, g_rinv);

    // 1. surprise + sorts + memory update
    k_surprise<<<BSROWS, 256>>>(hidden);
    k_sort_surprise<<<1, 1024>>>();
    k_sort_least<<<1, 1024, 65536>>>(imp, noise);
    k_copybuf<<<2048, 256>>>(membuf);
    k_scatter<<<BSROWS, 256>>>(hidden);

    // 2. split conversions (fp16)
    k_split1024<<<2048, 256>>>(hidden, (__half*)p_hsp, BSROWS * HD);
    k_split1024<<<1024, 256>>>(Wq, (__half*)p_wqsp, HD * HD);
    k_split1024<<<1024, 256>>>(Wk, (__half*)p_wksp, HD * HD);
    k_split1024<<<2048, 256>>>((const float*)p_buf, (__half*)p_bufsp, MSLOTS * HD);
    k_tsplit<<<dim3(32, 256), dim3(32, 8)>>>((const float*)p_buf, (__half*)p_bT);

    // 3. q = hidden @ Wq^T + bq -> split fp16 (3-seg: full precision)
    gemm_h<3><<<dim3(HD / 256, BSROWS / 128), 256, 2 * 98304>>>(
        (const __half*)p_hsp, (const __half*)p_wqsp, 2 * HD, 2 * HD, HD,
        bq, nullptr, 1.0f, nullptr, (__half*)p_qsp, 2 * HD, HD);

    // 4. mk = buf @ Wk^T + bk -> fp16 HI ONLY (3-seg)
    gemm_h<3><<<dim3(HD / 256, MSLOTS / 128), 256, 2 * 98304>>>(
        (const __half*)p_bufsp, (const __half*)p_wksp, 2 * HD, 2 * HD, HD,
        bk, nullptr, 1.0f, nullptr, (__half*)p_mksp, HD, 0);

    // 5. scores = q @ mk^T / 32 -> fp32 (2-seg: q split x mk hi)
    gemm_h<2><<<dim3(MSLOTS / 256, BSROWS / 128), 256, 2 * 65536>>>(
        (const __half*)p_qsp, (const __half*)p_mksp, 2 * HD, HD, HD,
        nullptr, nullptr, 0.03125f, (float*)p_sc, nullptr, MSLOTS, 0);

    // 6. softmax -> unnormalized exp split fp16 + 1/rowsum
    k_softmax<<<BSROWS, 256>>>();

    // 7. retrieved = (exp @ buf) * rinv -> d_out fp32 (2-seg: probs split x bT hi)
    gemm_h<2><<<dim3(HD / 256, BSROWS / 128), 256, 2 * 65536>>>(
        (const __half*)p_attn, (const __half*)p_bT, 2 * MSLOTS, MSLOTS, MSLOTS,
        nullptr, (const float*)p_rinv, 1.0f, out, nullptr, HD, 0);
}

// round 12
// speedup vs baseline: 3.9276x; 1.0269x over previous
#include <cuda_runtime.h>
#include <cuda_fp16.h>
#include <math.h>
#include <stdint.h>

#define BSROWS 4096   // B*S
#define HD     1024
#define MSLOTS 8192

// ---------------- device scratch (no allocations allowed) ----------------
__device__ float g_buf[MSLOTS * HD];                      // updated memory (fp32)
__device__ __half g_hsp [BSROWS * 2 * HD];                // hidden split  [4096,2048]
__device__ __half g_wqsp[HD * 2 * HD];                    // Wq split
__device__ __half g_wksp[HD * 2 * HD];                    // Wk split
__device__ __half g_bufsp[MSLOTS * 2 * HD];               // buf split     [8192,2048]
__device__ __half g_qsp [BSROWS * 2 * HD];                // q split       [4096,2048]
__device__ __half g_mksp[MSLOTS * HD];                    // mk HI ONLY    [8192,1024]
__device__ __half g_attnsp[(size_t)BSROWS * 2 * MSLOTS];  // exp(scores) split [4096,16384]
__device__ __half g_bTsp[HD * MSLOTS];                    // buf^T HI ONLY [1024,8192]
__device__ float g_surp[BSROWS];
__device__ int   g_top_i[BSROWS];
__device__ int   g_least[MSLOTS];
__device__ float g_rsum[BSROWS];                          // softmax row sums (atomic)
__device__ float g_rinv[BSROWS];                          // 1/rowsum

// ---------------- PTX helpers (base sm_103 ISA only) ----------------
__device__ __forceinline__ uint32_t smem_u32(const void* p) {
    uint32_t a;
    asm("{ .reg .u64 t; cvta.to.shared.u64 t, %1; cvt.u32.u64 %0, t; }" : "=r"(a) : "l"(p));
    return a;
}
#define SWZ128(x) ((x) ^ (((x) >> 3) & 0x70))
__device__ __forceinline__ void cpasync16(uint32_t dst, const void* src) {
    asm volatile("cp.async.cg.shared.global [%0], [%1], 16;"
                 :: "r"(dst), "l"(__cvta_generic_to_global(src)) : "memory");
}
__device__ __forceinline__ void cp_commit() {
    asm volatile("cp.async.commit_group;" ::: "memory");
}
__device__ __forceinline__ void cp_wait1() {
    asm volatile("cp.async.wait_group 1;" ::: "memory");
}
__device__ __forceinline__ void ldsm4(uint32_t& r0, uint32_t& r1, uint32_t& r2, uint32_t& r3,
                                      uint32_t addr) {
    asm volatile("ldmatrix.sync.aligned.m8n8.x4.shared.b16 {%0,%1,%2,%3}, [%4];"
                 : "=r"(r0), "=r"(r1), "=r"(r2), "=r"(r3) : "r"(addr));
}
__device__ __forceinline__ void mma16816(float* c, const uint32_t* a, const uint32_t* b) {
    asm volatile(
        "mma.sync.aligned.m16n8k16.row.col.f32.f16.f16.f32 "
        "{%0,%1,%2,%3}, {%4,%5,%6,%7}, {%8,%9}, {%0,%1,%2,%3};"
        : "+f"(c[0]), "+f"(c[1]), "+f"(c[2]), "+f"(c[3])
        : "r"(a[0]), "r"(a[1]), "r"(a[2]), "r"(a[3]), "r"(b[0]), "r"(b[1]));
}
__device__ __forceinline__ void split2h(float v, __half& h, __half& l) {
    h = __float2half_rn(v);
    l = __float2half_rn(v - __half2float(h));
}

// ---------------- fp16 split GEMM: C[M,N] = A (x) B^T ----------------
// Tile 128M x 256N, BK=64, 2 stages, 128B swizzled rows. Fragments hoisted.
// NSEG=3: (Ah,Bh)+(Al,Bh)+(Ah,Bl)   NSEG=2: (Ah,Bh)+(Al,Bh)
// Epilogue modes: fp32 out | split fp16 out | exp() + split fp16 + atomic rowsum.
template<int NSEG>
__global__ void __launch_bounds__(256, 1)
gemm_h(const __half* __restrict__ A, const __half* __restrict__ B,
       int ldA, int ldB, int Kseg,
       const float* __restrict__ bias, const float* __restrict__ rowscale, float alpha,
       float* __restrict__ outF, __half* __restrict__ outS, int ldOut, int loOff,
       float* __restrict__ rsum)
{
    constexpr int STB = 32768 + 32768 * (NSEG - 1);   // 2seg:64K  3seg:96K
    extern __shared__ char smem[];
    const uint32_t sb = smem_u32(smem);
    const int tid = threadIdx.x;
    const int wid = tid >> 5;
    const int lane = tid & 31;
    const int wm = wid & 1;      // 2 warps over M (64 rows)
    const int wn = wid >> 1;     // 4 warps over N (64 cols)
    const int row0 = blockIdx.y * 128;
    const int col0 = blockIdx.x * 256;
    const int C = Kseg >> 6;     // 64-wide k-chunks

    auto load_chunk = [&](int c) {
        const uint32_t st = sb + (c & 1) * STB;
        const int kcol = c << 6;
        #pragma unroll
        for (int i = 0; i < 4; i++) {            // A: 1024 16B units
            int u = tid + (i << 8);
            int r = u >> 3, uc = u & 7;
            uint32_t so = SWZ128(r * 128 + uc * 16);
            const __half* g = A + (size_t)(row0 + r) * ldA + kcol + uc * 8;
            cpasync16(st + so, g);                     // Ah
            cpasync16(st + 16384 + so, g + Kseg);      // Al
        }
        #pragma unroll
        for (int i = 0; i < 8; i++) {            // B: 2048 16B units
            int u = tid + (i << 8);
            int r = u >> 3, uc = u & 7;
            uint32_t so = SWZ128(r * 128 + uc * 16);
            const __half* g = B + (size_t)(col0 + r) * ldB + kcol + uc * 8;
            cpasync16(st + 32768 + so, g);             // Bh
            if (NSEG == 3) cpasync16(st + 65536 + so, g + Kseg);  // Bl
        }
    };

    float acc[4][8][4];
    #pragma unroll
    for (int mt = 0; mt < 4; mt++)
        #pragma unroll
        for (int nt = 0; nt < 8; nt++)
            #pragma unroll
            for (int i = 0; i < 4; i++) acc[mt][nt][i] = 0.0f;

    load_chunk(0); cp_commit();
    if (C > 1) load_chunk(1);
    cp_commit();

    for (int c = 0; c < C; c++) {
        cp_wait1();
        __syncthreads();
        const uint32_t stg = sb + (c & 1) * STB;
        #pragma unroll
        for (int ks = 0; ks < 4; ks++) {
            uint32_t ah[4][4], al[4][4], bh[8][2], bl[8][2];
            #pragma unroll
            for (int mt = 0; mt < 4; mt++) {
                int row = wm * 64 + mt * 16 + (lane & 15);
                int colb = (ks * 16 + ((lane >> 4) << 3)) * 2;
                uint32_t so = SWZ128(row * 128 + colb);
                ldsm4(ah[mt][0], ah[mt][1], ah[mt][2], ah[mt][3], stg + so);
                ldsm4(al[mt][0], al[mt][1], al[mt][2], al[mt][3], stg + 16384 + so);
            }
            #pragma unroll
            for (int nt2 = 0; nt2 < 4; nt2++) {
                int row = wn * 64 + nt2 * 16 + ((lane >> 4) << 3) + (lane & 7);
                int colb = (ks * 16 + (((lane >> 3) & 1) << 3)) * 2;
                uint32_t so = SWZ128(row * 128 + colb);
                ldsm4(bh[nt2*2][0], bh[nt2*2][1], bh[nt2*2+1][0], bh[nt2*2+1][1],
                      stg + 32768 + so);
                if (NSEG == 3)
                    ldsm4(bl[nt2*2][0], bl[nt2*2][1], bl[nt2*2+1][0], bl[nt2*2+1][1],
                          stg + 65536 + so);
            }
            #pragma unroll
            for (int mt = 0; mt < 4; mt++)
                #pragma unroll
                for (int nt = 0; nt < 8; nt++)
                    mma16816(acc[mt][nt], ah[mt], bh[nt]);
            #pragma unroll
            for (int mt = 0; mt < 4; mt++)
                #pragma unroll
                for (int nt = 0; nt < 8; nt++)
                    mma16816(acc[mt][nt], al[mt], bh[nt]);
            if (NSEG == 3) {
                #pragma unroll
                for (int mt = 0; mt < 4; mt++)
                    #pragma unroll
                    for (int nt = 0; nt < 8; nt++)
                        mma16816(acc[mt][nt], ah[mt], bl[nt]);
            }
        }
        __syncthreads();
        if (c + 2 < C) load_chunk(c + 2);
        cp_commit();                 // unconditional: keeps wait_group exact in tail
    }

    // ---- epilogue ----
    #pragma unroll
    for (int mt = 0; mt < 4; mt++) {
        const int r0g = row0 + wm * 64 + mt * 16 + (lane >> 2);
        #pragma unroll
        for (int half = 0; half < 2; half++) {
            const int rg = r0g + half * 8;
            const float rs = rowscale ? rowscale[rg] : 1.0f;
            float s = 0.0f;
            #pragma unroll
            for (int nt = 0; nt < 8; nt++) {
                const int cg = col0 + wn * 64 + nt * 8 + ((lane & 3) << 1);
                float v0 = acc[mt][nt][half * 2 + 0] * alpha;
                float v1 = acc[mt][nt][half * 2 + 1] * alpha;
                if (bias) { v0 += bias[cg]; v1 += bias[cg + 1]; }
                v0 *= rs; v1 *= rs;
                if (rsum) {                    // fused softmax numerator
                    v0 = __expf(v0); v1 = __expf(v1);
                    s += v0 + v1;
                }
                if (outF) {
                    *(float2*)(outF + (size_t)rg * ldOut + cg) = make_float2(v0, v1);
                } else {
                    __half h0, l0, h1, l1;
                    split2h(v0, h0, l0); split2h(v1, h1, l1);
                    __half2 hp; hp.x = h0; hp.y = h1;
                    *(__half2*)(outS + (size_t)rg * ldOut + cg) = hp;
                    if (loOff) {
                        __half2 lp; lp.x = l0; lp.y = l1;
                        *(__half2*)(outS + (size_t)rg * ldOut + loOff + cg) = lp;
                    }
                }
            }
            if (rsum) {
                s += __shfl_xor_sync(0xffffffffu, s, 1);
                s += __shfl_xor_sync(0xffffffffu, s, 2);
                if ((lane & 3) == 0) atomicAdd(&rsum[rg], s);
            }
        }
    }
}

// ---------------- pre/post kernels ----------------
__device__ __forceinline__ unsigned long long pack_kv(float key, unsigned idx) {
    unsigned u = __float_as_uint(key);
    u = (u & 0x80000000u) ? ~u : (u | 0x80000000u);
    return ((unsigned long long)u << 32) | idx;
}
__device__ __forceinline__ void bitonic_sort(unsigned long long* s, int n, int t, int nt) {
    for (int k = 2; k <= n; k <<= 1)
        for (int j = k >> 1; j > 0; j >>= 1) {
            for (int i = t; i < n; i += nt) {
                int ixj = i ^ j;
                if (ixj > i) {
                    unsigned long long a = s[i], b = s[ixj];
                    bool up = ((i & k) == 0);
                    if ((a > b) == up) { s[i] = b; s[ixj] = a; }
                }
            }
            __syncthreads();
        }
}

__global__ void k_surprise(const float* __restrict__ h) {
    int row = blockIdx.x, t = threadIdx.x;
    const float4* p = (const float4*)(h + (size_t)row * HD);
    float4 v = p[t];
    float s = v.x * v.x + v.y * v.y + v.z * v.z + v.w * v.w;
    #pragma unroll
    for (int o = 16; o; o >>= 1) s += __shfl_xor_sync(0xffffffffu, s, o);
    __shared__ float ws[8];
    if ((t & 31) == 0) ws[t >> 5] = s;
    __syncthreads();
    if (t < 8) {
        float x = ws[t];
        #pragma unroll
        for (int o = 4; o; o >>= 1) x += __shfl_xor_sync(0xffu, x, o);
        if (t == 0) g_surp[row] = 2.0f * sqrtf(x);
    }
    if (blockIdx.x == 0 && t < 256) {          // zero rowsum accumulators
        for (int i = t; i < BSROWS; i += 256) g_rsum[i] = 0.0f;
    }
}

__global__ void k_sort_surprise() {
    __shared__ unsigned long long sm[BSROWS];
    int t = threadIdx.x;
    for (int i = t; i < BSROWS; i += 1024) sm[i] = pack_kv(-g_surp[i], (unsigned)i);
    __syncthreads();
    bitonic_sort(sm, BSROWS, t, 1024);
    for (int i = t; i < BSROWS; i += 1024) g_top_i[i] = (int)(unsigned)sm[i];
}

__global__ void k_sort_least(const float* __restrict__ imp, const float* __restrict__ noise) {
    extern __shared__ unsigned long long dsm[];
    int t = threadIdx.x;
    for (int i = t; i < MSLOTS; i += 1024)
        dsm[i] = pack_kv(imp[i] + noise[i] * 1e-6f, (unsigned)i);
    __syncthreads();
    bitonic_sort(dsm, MSLOTS, t, 1024);
    for (int i = t; i < MSLOTS; i += 1024) g_least[i] = (int)(unsigned)dsm[i];
}

__global__ void k_copybuf(const float* __restrict__ src) {
    const float4* s = (const float4*)src;
    float4* d = (float4*)g_buf;
    size_t n = (size_t)MSLOTS * HD / 4;
    for (size_t i = blockIdx.x * 256ull + threadIdx.x; i < n; i += (size_t)gridDim.x * 256)
        d[i] = s[i];
}

__global__ void k_scatter(const float* __restrict__ hidden) {
    int i = blockIdx.x;
    int cand = g_top_i[i];
    if (g_surp[cand] > 64.0f) {
        int slot = g_least[i];
        const float4* src = (const float4*)(hidden + (size_t)cand * HD);
        float4* dst = (float4*)(g_buf + (size_t)slot * HD);
        dst[threadIdx.x] = src[threadIdx.x];
    }
}

// fp32 [R,1024] -> split fp16 [R,2048]
__global__ void k_split1024(const float* __restrict__ in, __half* __restrict__ out,
                            int total) {
    for (int e = blockIdx.x * 256 + threadIdx.x; e < total; e += gridDim.x * 256) {
        int r = e >> 10, k = e & 1023;
        __half h, l;
        split2h(in[e], h, l);
        out[((size_t)r << 11) + k] = h;
        out[((size_t)r << 11) + 1024 + k] = l;
    }
}

// merged buf prep: one read of g_buf -> bufsp (split, row-major) + bT (hi, transposed)
__global__ void k_bufprep(const float* __restrict__ in, __half* __restrict__ outsp,
                          __half* __restrict__ outT) {
    __shared__ float tile[32][33];
    int bc = blockIdx.x * 32, br = blockIdx.y * 32;
    int tx = threadIdx.x, ty = threadIdx.y;   // 32x8
    #pragma unroll
    for (int i = 0; i < 32; i += 8) {
        int r = br + ty + i, c = bc + tx;
        float v = in[(size_t)r * HD + c];
        tile[ty + i][tx] = v;
        __half h, l;
        split2h(v, h, l);
        outsp[((size_t)r << 11) + c] = h;
        outsp[((size_t)r << 11) + HD + c] = l;
    }
    __syncthreads();
    #pragma unroll
    for (int i = 0; i < 32; i += 8)
        outT[(size_t)(bc + ty + i) * MSLOTS + br + tx] = __float2half_rn(tile[tx][ty + i]);
}

// 1/rowsum
__global__ void k_rinv() {
    int i = blockIdx.x * 256 + threadIdx.x;
    if (i < BSROWS) g_rinv[i] = 1.0f / g_rsum[i];
}

// ---------------- host launch ----------------
extern "C" void kernel_launch(void* const* d_in, const int* in_sizes, int n_in,
                              void* d_out, int out_size) {
    const float* hidden = (const float*)d_in[0];
    const float* membuf = (const float*)d_in[1];
    const float* imp    = (const float*)d_in[2];
    const float* Wq     = (const float*)d_in[3];
    const float* bq     = (const float*)d_in[4];
    const float* Wk     = (const float*)d_in[5];
    const float* bk     = (const float*)d_in[6];
    const float* noise  = (const float*)d_in[7];
    float* out = (float*)d_out;

    cudaFuncSetAttribute(k_sort_least, cudaFuncAttributeMaxDynamicSharedMemorySize, 65536);
    cudaFuncSetAttribute(gemm_h<2>, cudaFuncAttributeMaxDynamicSharedMemorySize, 2 * 65536);
    cudaFuncSetAttribute(gemm_h<3>, cudaFuncAttributeMaxDynamicSharedMemorySize, 2 * 98304);

    void *p_buf, *p_hsp, *p_wqsp, *p_wksp, *p_bufsp, *p_qsp, *p_mksp, *p_attn, *p_bT, *p_rsum, *p_rinv;
    cudaGetSymbolAddress(&p_buf, g_buf);
    cudaGetSymbolAddress(&p_hsp, g_hsp);
    cudaGetSymbolAddress(&p_wqsp, g_wqsp);
    cudaGetSymbolAddress(&p_wksp, g_wksp);
    cudaGetSymbolAddress(&p_bufsp, g_bufsp);
    cudaGetSymbolAddress(&p_qsp, g_qsp);
    cudaGetSymbolAddress(&p_mksp, g_mksp);
    cudaGetSymbolAddress(&p_attn, g_attnsp);
    cudaGetSymbolAddress(&p_bT, g_bTsp);
    cudaGetSymbolAddress(&p_rsum, g_rsum);
    cudaGetSymbolAddress(&p_rinv, g_rinv);

    // 1. surprise (+ rsum zeroing) + sorts + memory update
    k_surprise<<<BSROWS, 256>>>(hidden);
    k_sort_surprise<<<1, 1024>>>();
    k_sort_least<<<1, 1024, 65536>>>(imp, noise);
    k_copybuf<<<2048, 256>>>(membuf);
    k_scatter<<<BSROWS, 256>>>(hidden);

    // 2. split conversions (fp16)
    k_split1024<<<2048, 256>>>(hidden, (__half*)p_hsp, BSROWS * HD);
    k_split1024<<<1024, 256>>>(Wq, (__half*)p_wqsp, HD * HD);
    k_split1024<<<1024, 256>>>(Wk, (__half*)p_wksp, HD * HD);
    k_bufprep<<<dim3(32, 256), dim3(32, 8)>>>((const float*)p_buf, (__half*)p_bufsp,
                                              (__half*)p_bT);

    // 3. q = hidden @ Wq^T + bq -> split fp16 (3-seg: full precision)
    gemm_h<3><<<dim3(HD / 256, BSROWS / 128), 256, 2 * 98304>>>(
        (const __half*)p_hsp, (const __half*)p_wqsp, 2 * HD, 2 * HD, HD,
        bq, nullptr, 1.0f, nullptr, (__half*)p_qsp, 2 * HD, HD, nullptr);

    // 4. mk = buf @ Wk^T + bk -> fp16 HI ONLY (3-seg)
    gemm_h<3><<<dim3(HD / 256, MSLOTS / 128), 256, 2 * 98304>>>(
        (const __half*)p_bufsp, (const __half*)p_wksp, 2 * HD, 2 * HD, HD,
        bk, nullptr, 1.0f, nullptr, (__half*)p_mksp, HD, 0, nullptr);

    // 5. exp(scores) = exp(q @ mk^T / 32) -> split fp16 + atomic rowsums (fused softmax)
    gemm_h<2><<<dim3(MSLOTS / 256, BSROWS / 128), 256, 2 * 65536>>>(
        (const __half*)p_qsp, (const __half*)p_mksp, 2 * HD, HD, HD,
        nullptr, nullptr, 0.03125f, nullptr, (__half*)p_attn, 2 * MSLOTS, MSLOTS,
        (float*)p_rsum);

    // 6. 1/rowsum
    k_rinv<<<BSROWS / 256, 256>>>();

    // 7. retrieved = (exp @ buf) * rinv -> d_out fp32 (2-seg: probs split x bT hi)
    gemm_h<2><<<dim3(HD / 256, BSROWS / 128), 256, 2 * 65536>>>(
        (const __half*)p_attn, (const __half*)p_bT, 2 * MSLOTS, MSLOTS, MSLOTS,
        nullptr, (const float*)p_rinv, 1.0f, out, nullptr, HD, 0, nullptr);
}

// round 15
// speedup vs baseline: 5.4733x; 1.3935x over previous
#include <cuda_runtime.h>
#include <cuda_fp16.h>
#include <math.h>
#include <stdint.h>

#define BSROWS 4096   // B*S
#define HD     1024
#define MSLOTS 8192

// ---------------- device scratch (no allocations allowed) ----------------
__device__ float g_buf[MSLOTS * HD];                      // updated memory (fp32)
__device__ __half g_hsp [BSROWS * 2 * HD];                // hidden split  [4096,2048]
__device__ __half g_wqsp[HD * 2 * HD];                    // Wq split
__device__ __half g_wksp[HD * 2 * HD];                    // Wk split
__device__ __half g_bufsp[MSLOTS * 2 * HD];               // buf split     [8192,2048]
__device__ __half g_qsp [BSROWS * HD];                    // q HI ONLY     [4096,1024]
__device__ __half g_mksp[MSLOTS * HD];                    // mk HI ONLY    [8192,1024]
__device__ __half g_attnsp[(size_t)BSROWS * MSLOTS];      // exp(scores) HI [4096,8192]
__device__ __half g_bTsp[HD * MSLOTS];                    // buf^T HI ONLY [1024,8192]
__device__ float g_surp[BSROWS];
__device__ int   g_top_i[BSROWS];
__device__ int   g_least[MSLOTS];
__device__ float g_rsum[BSROWS];                          // softmax row sums (atomic)
__device__ float g_rinv[BSROWS];                          // 1/rowsum

// ---------------- PTX helpers (base sm_103 ISA only) ----------------
__device__ __forceinline__ uint32_t smem_u32(const void* p) {
    uint32_t a;
    asm("{ .reg .u64 t; cvta.to.shared.u64 t, %1; cvt.u32.u64 %0, t; }" : "=r"(a) : "l"(p));
    return a;
}
#define SWZ128(x) ((x) ^ (((x) >> 3) & 0x70))
__device__ __forceinline__ void cpasync16(uint32_t dst, const void* src) {
    asm volatile("cp.async.cg.shared.global [%0], [%1], 16;"
                 :: "r"(dst), "l"(__cvta_generic_to_global(src)) : "memory");
}
__device__ __forceinline__ void cp_commit() {
    asm volatile("cp.async.commit_group;" ::: "memory");
}
__device__ __forceinline__ void cp_wait1() {
    asm volatile("cp.async.wait_group 1;" ::: "memory");
}
__device__ __forceinline__ void ldsm4(uint32_t& r0, uint32_t& r1, uint32_t& r2, uint32_t& r3,
                                      uint32_t addr) {
    asm volatile("ldmatrix.sync.aligned.m8n8.x4.shared.b16 {%0,%1,%2,%3}, [%4];"
                 : "=r"(r0), "=r"(r1), "=r"(r2), "=r"(r3) : "r"(addr));
}
__device__ __forceinline__ void mma16816(float* c, const uint32_t* a, const uint32_t* b) {
    asm volatile(
        "mma.sync.aligned.m16n8k16.row.col.f32.f16.f16.f32 "
        "{%0,%1,%2,%3}, {%4,%5,%6,%7}, {%8,%9}, {%0,%1,%2,%3};"
        : "+f"(c[0]), "+f"(c[1]), "+f"(c[2]), "+f"(c[3])
        : "r"(a[0]), "r"(a[1]), "r"(a[2]), "r"(a[3]), "r"(b[0]), "r"(b[1]));
}
__device__ __forceinline__ void split2h(float v, __half& h, __half& l) {
    h = __float2half_rn(v);
    l = __float2half_rn(v - __half2float(h));
}

// ---------------- fp16 split GEMM: C[M,N] = A (x) B^T ----------------
// Tile 128M x 256N, BK=64, 2 stages, 128B swizzled rows. Fragments hoisted.
// NSEG=3: (Ah,Bh)+(Al,Bh)+(Ah,Bl)   NSEG=1: (Ah,Bh) only
// Epilogue: fp32 out | fp16 out (hi or hi+lo) | exp() + fp16 + atomic rowsum.
template<int NSEG>
__global__ void __launch_bounds__(256, 1)
gemm_h(const __half* __restrict__ A, const __half* __restrict__ B,
       int ldA, int ldB, int Kseg,
       const float* __restrict__ bias, const float* __restrict__ rowscale, float alpha,
       float* __restrict__ outF, __half* __restrict__ outS, int ldOut, int loOff,
       float* __restrict__ rsum)
{
    constexpr int STB  = (NSEG == 1) ? 49152 : 98304;  // per-stage bytes
    constexpr int BOFF = (NSEG == 1) ? 16384 : 32768;  // Bh offset in stage
    extern __shared__ char smem[];
    const uint32_t sb = smem_u32(smem);
    const int tid = threadIdx.x;
    const int wid = tid >> 5;
    const int lane = tid & 31;
    const int wm = wid & 1;      // 2 warps over M (64 rows)
    const int wn = wid >> 1;     // 4 warps over N (64 cols)
    const int row0 = blockIdx.y * 128;
    const int col0 = blockIdx.x * 256;
    const int C = Kseg >> 6;     // 64-wide k-chunks

    auto load_chunk = [&](int c) {
        const uint32_t st = sb + (c & 1) * STB;
        const int kcol = c << 6;
        #pragma unroll
        for (int i = 0; i < 4; i++) {            // A: 1024 16B units
            int u = tid + (i << 8);
            int r = u >> 3, uc = u & 7;
            uint32_t so = SWZ128(r * 128 + uc * 16);
            const __half* g = A + (size_t)(row0 + r) * ldA + kcol + uc * 8;
            cpasync16(st + so, g);                                  // Ah
            if (NSEG >= 2) cpasync16(st + 16384 + so, g + Kseg);    // Al
        }
        #pragma unroll
        for (int i = 0; i < 8; i++) {            // B: 2048 16B units
            int u = tid + (i << 8);
            int r = u >> 3, uc = u & 7;
            uint32_t so = SWZ128(r * 128 + uc * 16);
            const __half* g = B + (size_t)(col0 + r) * ldB + kcol + uc * 8;
            cpasync16(st + BOFF + so, g);                           // Bh
            if (NSEG == 3) cpasync16(st + 65536 + so, g + Kseg);    // Bl
        }
    };

    float acc[4][8][4];
    #pragma unroll
    for (int mt = 0; mt < 4; mt++)
        #pragma unroll
        for (int nt = 0; nt < 8; nt++)
            #pragma unroll
            for (int i = 0; i < 4; i++) acc[mt][nt][i] = 0.0f;

    load_chunk(0); cp_commit();
    if (C > 1) load_chunk(1);
    cp_commit();

    for (int c = 0; c < C; c++) {
        cp_wait1();
        __syncthreads();
        const uint32_t stg = sb + (c & 1) * STB;
        #pragma unroll
        for (int ks = 0; ks < 4; ks++) {
            uint32_t ah[4][4], al[4][4], bh[8][2], bl[8][2];
            #pragma unroll
            for (int mt = 0; mt < 4; mt++) {
                int row = wm * 64 + mt * 16 + (lane & 15);
                int colb = (ks * 16 + ((lane >> 4) << 3)) * 2;
                uint32_t so = SWZ128(row * 128 + colb);
                ldsm4(ah[mt][0], ah[mt][1], ah[mt][2], ah[mt][3], stg + so);
                if (NSEG >= 2)
                    ldsm4(al[mt][0], al[mt][1], al[mt][2], al[mt][3], stg + 16384 + so);
            }
            #pragma unroll
            for (int nt2 = 0; nt2 < 4; nt2++) {
                int row = wn * 64 + nt2 * 16 + ((lane >> 4) << 3) + (lane & 7);
                int colb = (ks * 16 + (((lane >> 3) & 1) << 3)) * 2;
                uint32_t so = SWZ128(row * 128 + colb);
                ldsm4(bh[nt2*2][0], bh[nt2*2][1], bh[nt2*2+1][0], bh[nt2*2+1][1],
                      stg + BOFF + so);
                if (NSEG == 3)
                    ldsm4(bl[nt2*2][0], bl[nt2*2][1], bl[nt2*2+1][0], bl[nt2*2+1][1],
                          stg + 65536 + so);
            }
            #pragma unroll
            for (int mt = 0; mt < 4; mt++)
                #pragma unroll
                for (int nt = 0; nt < 8; nt++)
                    mma16816(acc[mt][nt], ah[mt], bh[nt]);
            if (NSEG >= 2) {
                #pragma unroll
                for (int mt = 0; mt < 4; mt++)
                    #pragma unroll
                    for (int nt = 0; nt < 8; nt++)
                        mma16816(acc[mt][nt], al[mt], bh[nt]);
            }
            if (NSEG == 3) {
                #pragma unroll
                for (int mt = 0; mt < 4; mt++)
                    #pragma unroll
                    for (int nt = 0; nt < 8; nt++)
                        mma16816(acc[mt][nt], ah[mt], bl[nt]);
            }
        }
        __syncthreads();
        if (c + 2 < C) load_chunk(c + 2);
        cp_commit();                 // unconditional: keeps wait_group exact in tail
    }

    // ---- epilogue ----
    #pragma unroll
    for (int mt = 0; mt < 4; mt++) {
        const int r0g = row0 + wm * 64 + mt * 16 + (lane >> 2);
        #pragma unroll
        for (int half = 0; half < 2; half++) {
            const int rg = r0g + half * 8;
            const float rs = rowscale ? rowscale[rg] : 1.0f;
            float s = 0.0f;
            #pragma unroll
            for (int nt = 0; nt < 8; nt++) {
                const int cg = col0 + wn * 64 + nt * 8 + ((lane & 3) << 1);
                float v0 = acc[mt][nt][half * 2 + 0] * alpha;
                float v1 = acc[mt][nt][half * 2 + 1] * alpha;
                if (bias) { v0 += bias[cg]; v1 += bias[cg + 1]; }
                v0 *= rs; v1 *= rs;
                if (rsum) {                    // fused softmax numerator
                    v0 = __expf(v0); v1 = __expf(v1);
                    s += v0 + v1;
                }
                if (outF) {
                    *(float2*)(outF + (size_t)rg * ldOut + cg) = make_float2(v0, v1);
                } else {
                    __half2 hp;
                    hp.x = __float2half_rn(v0); hp.y = __float2half_rn(v1);
                    *(__half2*)(outS + (size_t)rg * ldOut + cg) = hp;
                    if (loOff) {
                        __half2 lp;
                        lp.x = __float2half_rn(v0 - __half2float(hp.x));
                        lp.y = __float2half_rn(v1 - __half2float(hp.y));
                        *(__half2*)(outS + (size_t)rg * ldOut + loOff + cg) = lp;
                    }
                }
            }
            if (rsum) {
                s += __shfl_xor_sync(0xffffffffu, s, 1);
                s += __shfl_xor_sync(0xffffffffu, s, 2);
                if ((lane & 3) == 0) atomicAdd(&rsum[rg], s);
            }
        }
    }
}

// ---------------- pre/post kernels ----------------
__device__ __forceinline__ unsigned long long pack_kv(float key, unsigned idx) {
    unsigned u = __float_as_uint(key);
    u = (u & 0x80000000u) ? ~u : (u | 0x80000000u);
    return ((unsigned long long)u << 32) | idx;
}
__device__ __forceinline__ void bitonic_sort(unsigned long long* s, int n, int t, int nt) {
    for (int k = 2; k <= n; k <<= 1)
        for (int j = k >> 1; j > 0; j >>= 1) {
            for (int i = t; i < n; i += nt) {
                int ixj = i ^ j;
                if (ixj > i) {
                    unsigned long long a = s[i], b = s[ixj];
                    bool up = ((i & k) == 0);
                    if ((a > b) == up) { s[i] = b; s[ixj] = a; }
                }
            }
            __syncthreads();
        }
}

__global__ void k_surprise(const float* __restrict__ h) {
    int row = blockIdx.x, t = threadIdx.x;
    const float4* p = (const float4*)(h + (size_t)row * HD);
    float4 v = p[t];
    float s = v.x * v.x + v.y * v.y + v.z * v.z + v.w * v.w;
    #pragma unroll
    for (int o = 16; o; o >>= 1) s += __shfl_xor_sync(0xffffffffu, s, o);
    __shared__ float ws[8];
    if ((t & 31) == 0) ws[t >> 5] = s;
    __syncthreads();
    if (t < 8) {
        float x = ws[t];
        #pragma unroll
        for (int o = 4; o; o >>= 1) x += __shfl_xor_sync(0xffu, x, o);
        if (t == 0) g_surp[row] = 2.0f * sqrtf(x);
    }
    if (blockIdx.x == 0) {                       // zero rowsum accumulators
        for (int i = t; i < BSROWS; i += 256) g_rsum[i] = 0.0f;
    }
}

__global__ void k_sort_surprise() {
    __shared__ unsigned long long sm[BSROWS];
    int t = threadIdx.x;
    for (int i = t; i < BSROWS; i += 1024) sm[i] = pack_kv(-g_surp[i], (unsigned)i);
    __syncthreads();
    bitonic_sort(sm, BSROWS, t, 1024);
    for (int i = t; i < BSROWS; i += 1024) g_top_i[i] = (int)(unsigned)sm[i];
}

__global__ void k_sort_least(const float* __restrict__ imp, const float* __restrict__ noise) {
    extern __shared__ unsigned long long dsm[];
    int t = threadIdx.x;
    for (int i = t; i < MSLOTS; i += 1024)
        dsm[i] = pack_kv(imp[i] + noise[i] * 1e-6f, (unsigned)i);
    __syncthreads();
    bitonic_sort(dsm, MSLOTS, t, 1024);
    for (int i = t; i < MSLOTS; i += 1024) g_least[i] = (int)(unsigned)dsm[i];
}

__global__ void k_copybuf(const float* __restrict__ src) {
    const float4* s = (const float4*)src;
    float4* d = (float4*)g_buf;
    size_t n = (size_t)MSLOTS * HD / 4;
    for (size_t i = blockIdx.x * 256ull + threadIdx.x; i < n; i += (size_t)gridDim.x * 256)
        d[i] = s[i];
}

__global__ void k_scatter(const float* __restrict__ hidden) {
    int i = blockIdx.x;
    int cand = g_top_i[i];
    if (g_surp[cand] > 64.0f) {
        int slot = g_least[i];
        const float4* src = (const float4*)(hidden + (size_t)cand * HD);
        float4* dst = (float4*)(g_buf + (size_t)slot * HD);
        dst[threadIdx.x] = src[threadIdx.x];
    }
}

// fp32 [R,1024] -> split fp16 [R,2048]
__global__ void k_split1024(const float* __restrict__ in, __half* __restrict__ out,
                            int total) {
    for (int e = blockIdx.x * 256 + threadIdx.x; e < total; e += gridDim.x * 256) {
        int r = e >> 10, k = e & 1023;
        __half h, l;
        split2h(in[e], h, l);
        out[((size_t)r << 11) + k] = h;
        out[((size_t)r << 11) + 1024 + k] = l;
    }
}

// merged buf prep: one read of g_buf -> bufsp (split, row-major) + bT (hi, transposed)
__global__ void k_bufprep(const float* __restrict__ in, __half* __restrict__ outsp,
                          __half* __restrict__ outT) {
    __shared__ float tile[32][33];
    int bc = blockIdx.x * 32, br = blockIdx.y * 32;
    int tx = threadIdx.x, ty = threadIdx.y;   // 32x8
    #pragma unroll
    for (int i = 0; i < 32; i += 8) {
        int r = br + ty + i, c = bc + tx;
        float v = in[(size_t)r * HD + c];
        tile[ty + i][tx] = v;
        __half h, l;
        split2h(v, h, l);
        outsp[((size_t)r << 11) + c] = h;
        outsp[((size_t)r << 11) + HD + c] = l;
    }
    __syncthreads();
    #pragma unroll
    for (int i = 0; i < 32; i += 8)
        outT[(size_t)(bc + ty + i) * MSLOTS + br + tx] = __float2half_rn(tile[tx][ty + i]);
}

// 1/rowsum
__global__ void k_rinv() {
    int i = blockIdx.x * 256 + threadIdx.x;
    if (i < BSROWS) g_rinv[i] = 1.0f / g_rsum[i];
}

// ---------------- host launch ----------------
extern "C" void kernel_launch(void* const* d_in, const int* in_sizes, int n_in,
                              void* d_out, int out_size) {
    const float* hidden = (const float*)d_in[0];
    const float* membuf = (const float*)d_in[1];
    const float* imp    = (const float*)d_in[2];
    const float* Wq     = (const float*)d_in[3];
    const float* bq     = (const float*)d_in[4];
    const float* Wk     = (const float*)d_in[5];
    const float* bk     = (const float*)d_in[6];
    const float* noise  = (const float*)d_in[7];
    float* out = (float*)d_out;

    cudaFuncSetAttribute(k_sort_least, cudaFuncAttributeMaxDynamicSharedMemorySize, 65536);
    cudaFuncSetAttribute(gemm_h<1>, cudaFuncAttributeMaxDynamicSharedMemorySize, 2 * 49152);
    cudaFuncSetAttribute(gemm_h<3>, cudaFuncAttributeMaxDynamicSharedMemorySize, 2 * 98304);

    void *p_buf, *p_hsp, *p_wqsp, *p_wksp, *p_bufsp, *p_qsp, *p_mksp, *p_attn, *p_bT, *p_rsum, *p_rinv;
    cudaGetSymbolAddress(&p_buf, g_buf);
    cudaGetSymbolAddress(&p_hsp, g_hsp);
    cudaGetSymbolAddress(&p_wqsp, g_wqsp);
    cudaGetSymbolAddress(&p_wksp, g_wksp);
    cudaGetSymbolAddress(&p_bufsp, g_bufsp);
    cudaGetSymbolAddress(&p_qsp, g_qsp);
    cudaGetSymbolAddress(&p_mksp, g_mksp);
    cudaGetSymbolAddress(&p_attn, g_attnsp);
    cudaGetSymbolAddress(&p_bT, g_bTsp);
    cudaGetSymbolAddress(&p_rsum, g_rsum);
    cudaGetSymbolAddress(&p_rinv, g_rinv);

    // 1. surprise (+ rsum zeroing) + sorts + memory update
    k_surprise<<<BSROWS, 256>>>(hidden);
    k_sort_surprise<<<1, 1024>>>();
    k_sort_least<<<1, 1024, 65536>>>(imp, noise);
    k_copybuf<<<2048, 256>>>(membuf);
    k_scatter<<<BSROWS, 256>>>(hidden);

    // 2. split conversions (fp16)
    k_split1024<<<2048, 256>>>(hidden, (__half*)p_hsp, BSROWS * HD);
    k_split1024<<<1024, 256>>>(Wq, (__half*)p_wqsp, HD * HD);
    k_split1024<<<1024, 256>>>(Wk, (__half*)p_wksp, HD * HD);
    k_bufprep<<<dim3(32, 256), dim3(32, 8)>>>((const float*)p_buf, (__half*)p_bufsp,
                                              (__half*)p_bT);

    // 3. q = hidden @ Wq^T + bq -> fp16 HI ONLY (3-seg: full-precision accumulate)
    gemm_h<3><<<dim3(HD / 256, BSROWS / 128), 256, 2 * 98304>>>(
        (const __half*)p_hsp, (const __half*)p_wqsp, 2 * HD, 2 * HD, HD,
        bq, nullptr, 1.0f, nullptr, (__half*)p_qsp, HD, 0, nullptr);

    // 4. mk = buf @ Wk^T + bk -> fp16 HI ONLY (3-seg)
    gemm_h<3><<<dim3(HD / 256, MSLOTS / 128), 256, 2 * 98304>>>(
        (const __half*)p_bufsp, (const __half*)p_wksp, 2 * HD, 2 * HD, HD,
        bk, nullptr, 1.0f, nullptr, (__half*)p_mksp, HD, 0, nullptr);

    // 5. exp(scores) = exp(qh @ mkh^T / 32) -> fp16 HI + atomic rowsums (1-seg)
    gemm_h<1><<<dim3(MSLOTS / 256, BSROWS / 128), 256, 2 * 49152>>>(
        (const __half*)p_qsp, (const __half*)p_mksp, HD, HD, HD,
        nullptr, nullptr, 0.03125f, nullptr, (__half*)p_attn, MSLOTS, 0,
        (float*)p_rsum);

    // 6. 1/rowsum
    k_rinv<<<BSROWS / 256, 256>>>();

    // 7. retrieved = (exp_hi @ bT_hi) * rinv -> d_out fp32 (1-seg)
    gemm_h<1><<<dim3(HD / 256, BSROWS / 128), 256, 2 * 49152>>>(
        (const __half*)p_attn, (const __half*)p_bT, MSLOTS, MSLOTS, MSLOTS,
        nullptr, (const float*)p_rinv, 1.0f, out, nullptr, HD, 0, nullptr);
}

// round 17
// speedup vs baseline: 7.2469x; 1.3240x over previous
#include <cuda_runtime.h>
#include <cuda_fp16.h>
#include <math.h>
#include <stdint.h>

#define BSROWS 4096   // B*S
#define HD     1024
#define MSLOTS 8192

// ---------------- device scratch (no allocations allowed) ----------------
__device__ __half g_hh  [BSROWS * HD];                    // hidden fp16   [4096,1024]
__device__ __half g_wqh [HD * HD];                        // Wq fp16
__device__ __half g_wkh [HD * HD];                        // Wk fp16
__device__ __half g_bufh[MSLOTS * HD];                    // new buffer fp16 [8192,1024]
__device__ __half g_bTh [HD * MSLOTS];                    // new buffer^T fp16 [1024,8192]
__device__ __half g_qh  [BSROWS * HD];                    // q fp16        [4096,1024]
__device__ __half g_mkh [MSLOTS * HD];                    // mk fp16       [8192,1024]
__device__ __half g_attnh[(size_t)BSROWS * MSLOTS];       // exp(scores) fp16 [4096,8192]
__device__ float g_surp[BSROWS];
__device__ int   g_least[MSLOTS];                         // slots by importance asc
__device__ int   g_rank[BSROWS];                          // valid candidates (arbitrary order)
__device__ int   g_map[MSLOTS];                           // slot -> candidate (-1 = keep)
__device__ int   g_cnt;                                   // number of valid candidates
__device__ float g_rsum[BSROWS];                          // softmax row sums (atomic)

// ---------------- PTX helpers (base sm_103 ISA only) ----------------
__device__ __forceinline__ uint32_t smem_u32(const void* p) {
    uint32_t a;
    asm("{ .reg .u64 t; cvta.to.shared.u64 t, %1; cvt.u32.u64 %0, t; }" : "=r"(a) : "l"(p));
    return a;
}
#define SWZ128(x) ((x) ^ (((x) >> 3) & 0x70))
__device__ __forceinline__ void cpasync16(uint32_t dst, const void* src) {
    asm volatile("cp.async.cg.shared.global [%0], [%1], 16;"
                 :: "r"(dst), "l"(__cvta_generic_to_global(src)) : "memory");
}
__device__ __forceinline__ void cp_commit() {
    asm volatile("cp.async.commit_group;" ::: "memory");
}
__device__ __forceinline__ void cp_wait1() {
    asm volatile("cp.async.wait_group 1;" ::: "memory");
}
__device__ __forceinline__ void ldsm4(uint32_t& r0, uint32_t& r1, uint32_t& r2, uint32_t& r3,
                                      uint32_t addr) {
    asm volatile("ldmatrix.sync.aligned.m8n8.x4.shared.b16 {%0,%1,%2,%3}, [%4];"
                 : "=r"(r0), "=r"(r1), "=r"(r2), "=r"(r3) : "r"(addr));
}
__device__ __forceinline__ void mma16816(float* c, const uint32_t* a, const uint32_t* b) {
    asm volatile(
        "mma.sync.aligned.m16n8k16.row.col.f32.f16.f16.f32 "
        "{%0,%1,%2,%3}, {%4,%5,%6,%7}, {%8,%9}, {%0,%1,%2,%3};"
        : "+f"(c[0]), "+f"(c[1]), "+f"(c[2]), "+f"(c[3])
        : "r"(a[0]), "r"(a[1]), "r"(a[2]), "r"(a[3]), "r"(b[0]), "r"(b[1]));
}

// ---------------- fp16 GEMM: C[M,N] = A[M,K] (x) B[N,K]^T ----------------
// Tile 128M x 256N, BK=64, 2 stages, 128B swizzled rows, fragments hoisted.
// Epilogue: fp32 out | fp16 out | exp() + fp16 + atomic rowsum; rowscale w/ recip.
#define STB 49152          // per-stage bytes: A 16KB + B 32KB
__global__ void __launch_bounds__(256, 1)
gemm_h(const __half* __restrict__ A, const __half* __restrict__ B,
       int ldA, int ldB, int K,
       const float* __restrict__ bias, const float* __restrict__ rowscale, int recip,
       float alpha, float* __restrict__ outF, __half* __restrict__ outS, int ldOut,
       float* __restrict__ rsum)
{
    extern __shared__ char smem[];
    const uint32_t sb = smem_u32(smem);
    const int tid = threadIdx.x;
    const int wid = tid >> 5;
    const int lane = tid & 31;
    const int wm = wid & 1;      // 2 warps over M (64 rows)
    const int wn = wid >> 1;     // 4 warps over N (64 cols)
    const int row0 = blockIdx.y * 128;
    const int col0 = blockIdx.x * 256;
    const int C = K >> 6;        // 64-wide k-chunks

    auto load_chunk = [&](int c) {
        const uint32_t st = sb + (c & 1) * STB;
        const int kcol = c << 6;
        #pragma unroll
        for (int i = 0; i < 4; i++) {            // A: 1024 16B units
            int u = tid + (i << 8);
            int r = u >> 3, uc = u & 7;
            cpasync16(st + SWZ128(r * 128 + uc * 16),
                      A + (size_t)(row0 + r) * ldA + kcol + uc * 8);
        }
        #pragma unroll
        for (int i = 0; i < 8; i++) {            // B: 2048 16B units
            int u = tid + (i << 8);
            int r = u >> 3, uc = u & 7;
            cpasync16(st + 16384 + SWZ128(r * 128 + uc * 16),
                      B + (size_t)(col0 + r) * ldB + kcol + uc * 8);
        }
    };

    float acc[4][8][4];
    #pragma unroll
    for (int mt = 0; mt < 4; mt++)
        #pragma unroll
        for (int nt = 0; nt < 8; nt++)
            #pragma unroll
            for (int i = 0; i < 4; i++) acc[mt][nt][i] = 0.0f;

    load_chunk(0); cp_commit();
    if (C > 1) load_chunk(1);
    cp_commit();

    for (int c = 0; c < C; c++) {
        cp_wait1();
        __syncthreads();
        const uint32_t stg = sb + (c & 1) * STB;
        #pragma unroll
        for (int ks = 0; ks < 4; ks++) {
            uint32_t ah[4][4], bh[8][2];
            #pragma unroll
            for (int mt = 0; mt < 4; mt++) {
                int row = wm * 64 + mt * 16 + (lane & 15);
                int colb = (ks * 16 + ((lane >> 4) << 3)) * 2;
                ldsm4(ah[mt][0], ah[mt][1], ah[mt][2], ah[mt][3],
                      stg + SWZ128(row * 128 + colb));
            }
            #pragma unroll
            for (int nt2 = 0; nt2 < 4; nt2++) {
                int row = wn * 64 + nt2 * 16 + ((lane >> 4) << 3) + (lane & 7);
                int colb = (ks * 16 + (((lane >> 3) & 1) << 3)) * 2;
                ldsm4(bh[nt2*2][0], bh[nt2*2][1], bh[nt2*2+1][0], bh[nt2*2+1][1],
                      stg + 16384 + SWZ128(row * 128 + colb));
            }
            #pragma unroll
            for (int mt = 0; mt < 4; mt++)
                #pragma unroll
                for (int nt = 0; nt < 8; nt++)
                    mma16816(acc[mt][nt], ah[mt], bh[nt]);
        }
        __syncthreads();
        if (c + 2 < C) load_chunk(c + 2);
        cp_commit();                 // unconditional: keeps wait_group exact in tail
    }

    // ---- epilogue ----
    #pragma unroll
    for (int mt = 0; mt < 4; mt++) {
        const int r0g = row0 + wm * 64 + mt * 16 + (lane >> 2);
        #pragma unroll
        for (int half = 0; half < 2; half++) {
            const int rg = r0g + half * 8;
            float rs = 1.0f;
            if (rowscale) { rs = rowscale[rg]; if (recip) rs = 1.0f / rs; }
            float s = 0.0f;
            #pragma unroll
            for (int nt = 0; nt < 8; nt++) {
                const int cg = col0 + wn * 64 + nt * 8 + ((lane & 3) << 1);
                float v0 = acc[mt][nt][half * 2 + 0] * alpha;
                float v1 = acc[mt][nt][half * 2 + 1] * alpha;
                if (bias) { v0 += bias[cg]; v1 += bias[cg + 1]; }
                v0 *= rs; v1 *= rs;
                if (rsum) {                    // fused softmax numerator
                    v0 = __expf(v0); v1 = __expf(v1);
                    s += v0 + v1;
                }
                if (outF) {
                    *(float2*)(outF + (size_t)rg * ldOut + cg) = make_float2(v0, v1);
                } else {
                    __half2 hp;
                    hp.x = __float2half_rn(v0); hp.y = __float2half_rn(v1);
                    *(__half2*)(outS + (size_t)rg * ldOut + cg) = hp;
                }
            }
            if (rsum) {
                s += __shfl_xor_sync(0xffffffffu, s, 1);
                s += __shfl_xor_sync(0xffffffffu, s, 2);
                if ((lane & 3) == 0) atomicAdd(&rsum[rg], s);
            }
        }
    }
}

// ---------------- pre/post kernels ----------------
__device__ __forceinline__ unsigned long long pack_kv(float key, unsigned idx) {
    unsigned u = __float_as_uint(key);
    u = (u & 0x80000000u) ? ~u : (u | 0x80000000u);
    return ((unsigned long long)u << 32) | idx;
}
__device__ __forceinline__ void bitonic_sort(unsigned long long* s, int n, int t, int nt) {
    for (int k = 2; k <= n; k <<= 1)
        for (int j = k >> 1; j > 0; j >>= 1) {
            for (int i = t; i < n; i += nt) {
                int ixj = i ^ j;
                if (ixj > i) {
                    unsigned long long a = s[i], b = s[ixj];
                    bool up = ((i & k) == 0);
                    if ((a > b) == up) { s[i] = b; s[ixj] = a; }
                }
            }
            __syncthreads();
        }
}

// surprise per row + hidden -> fp16 + init rsum/map/cnt
__global__ void k_surprise(const float* __restrict__ h) {
    int row = blockIdx.x, t = threadIdx.x;
    const float4* p = (const float4*)(h + (size_t)row * HD);
    float4 v = p[t];
    __half2 a, b;
    a.x = __float2half_rn(v.x); a.y = __float2half_rn(v.y);
    b.x = __float2half_rn(v.z); b.y = __float2half_rn(v.w);
    *(__half2*)(g_hh + (size_t)row * HD + 4 * t) = a;
    *(__half2*)(g_hh + (size_t)row * HD + 4 * t + 2) = b;
    float s = v.x * v.x + v.y * v.y + v.z * v.z + v.w * v.w;
    #pragma unroll
    for (int o = 16; o; o >>= 1) s += __shfl_xor_sync(0xffffffffu, s, o);
    __shared__ float ws[8];
    if ((t & 31) == 0) ws[t >> 5] = s;
    __syncthreads();
    if (t < 8) {
        float x = ws[t];
        #pragma unroll
        for (int o = 4; o; o >>= 1) x += __shfl_xor_sync(0xffu, x, o);
        if (t == 0) g_surp[row] = 2.0f * sqrtf(x);
    }
    if (blockIdx.x == 0)
        for (int i = t; i < BSROWS; i += 256) g_rsum[i] = 0.0f;
    if (blockIdx.x == 1)
        for (int i = t; i < MSLOTS; i += 256) g_map[i] = -1;
    if (blockIdx.x == 2 && t == 0) g_cnt = 0;
}

// fp32 -> fp16 flat convert
__global__ void k_convhi(const float* __restrict__ in, __half* __restrict__ out, int n4) {
    for (int i = blockIdx.x * 256 + threadIdx.x; i < n4; i += gridDim.x * 256) {
        float4 v = ((const float4*)in)[i];
        __half2 a, b;
        a.x = __float2half_rn(v.x); a.y = __float2half_rn(v.y);
        b.x = __float2half_rn(v.z); b.y = __float2half_rn(v.w);
        *(__half2*)(out + 4 * (size_t)i) = a;
        *(__half2*)(out + 4 * (size_t)i + 2) = b;
    }
}

__global__ void k_sort_least(const float* __restrict__ imp, const float* __restrict__ noise) {
    extern __shared__ unsigned long long dsm[];
    int t = threadIdx.x;
    for (int i = t; i < MSLOTS; i += 1024)
        dsm[i] = pack_kv(imp[i] + noise[i] * 1e-6f, (unsigned)i);
    __syncthreads();
    bitonic_sort(dsm, MSLOTS, t, 1024);
    for (int i = t; i < MSLOTS; i += 1024) g_least[i] = (int)(unsigned)dsm[i];
}

// valid candidates -> arbitrary ranks (pairing is free: output is row-multiset invariant)
__global__ void k_filter() {
    int i = blockIdx.x * 256 + threadIdx.x;
    if (i < BSROWS && g_surp[i] > 64.0f) {
        int r = atomicAdd(&g_cnt, 1);
        g_rank[r] = i;
    }
}

// slot -> candidate map for the V least-important slots
__global__ void k_mapbuild() {
    int r = blockIdx.x * 256 + threadIdx.x;
    if (r < BSROWS && r < g_cnt) g_map[g_least[r]] = g_rank[r];
}

// fused buffer materialization: membuf/hidden (per map) -> bufh fp16 + bT fp16
__global__ void k_bufprep(const float* __restrict__ membuf, const float* __restrict__ hidden) {
    __shared__ float tile[32][33];
    int bc = blockIdx.x * 32, br = blockIdx.y * 32;
    int tx = threadIdx.x, ty = threadIdx.y;   // 32x8
    #pragma unroll
    for (int i = 0; i < 32; i += 8) {
        int r = br + ty + i;
        int c = g_map[r];
        const float* src = (c >= 0) ? hidden + (size_t)c * HD : membuf + (size_t)r * HD;
        float v = src[bc + tx];
        tile[ty + i][tx] = v;
        g_bufh[(size_t)r * HD + bc + tx] = __float2half_rn(v);
    }
    __syncthreads();
    #pragma unroll
    for (int i = 0; i < 32; i += 8)
        g_bTh[(size_t)(bc + ty + i) * MSLOTS + br + tx] = __float2half_rn(tile[tx][ty + i]);
}

// ---------------- host launch ----------------
extern "C" void kernel_launch(void* const* d_in, const int* in_sizes, int n_in,
                              void* d_out, int out_size) {
    const float* hidden = (const float*)d_in[0];
    const float* membuf = (const float*)d_in[1];
    const float* imp    = (const float*)d_in[2];
    const float* Wq     = (const float*)d_in[3];
    const float* bq     = (const float*)d_in[4];
    const float* Wk     = (const float*)d_in[5];
    const float* bk     = (const float*)d_in[6];
    const float* noise  = (const float*)d_in[7];
    float* out = (float*)d_out;

    cudaFuncSetAttribute(k_sort_least, cudaFuncAttributeMaxDynamicSharedMemorySize, 65536);
    cudaFuncSetAttribute(gemm_h, cudaFuncAttributeMaxDynamicSharedMemorySize, 2 * STB);

    void *p_hh, *p_wqh, *p_wkh, *p_bufh, *p_bTh, *p_qh, *p_mkh, *p_attn, *p_rsum;
    cudaGetSymbolAddress(&p_hh, g_hh);
    cudaGetSymbolAddress(&p_wqh, g_wqh);
    cudaGetSymbolAddress(&p_wkh, g_wkh);
    cudaGetSymbolAddress(&p_bufh, g_bufh);
    cudaGetSymbolAddress(&p_bTh, g_bTh);
    cudaGetSymbolAddress(&p_qh, g_qh);
    cudaGetSymbolAddress(&p_mkh, g_mkh);
    cudaGetSymbolAddress(&p_attn, g_attnh);
    cudaGetSymbolAddress(&p_rsum, g_rsum);

    // 1. surprise + h->fp16 + state init
    k_surprise<<<BSROWS, 256>>>(hidden);
    // 2. weight conversions + slot sort + candidate filter + map + buffer build
    k_convhi<<<512, 256>>>(Wq, (__half*)p_wqh, HD * HD / 4);
    k_convhi<<<512, 256>>>(Wk, (__half*)p_wkh, HD * HD / 4);
    k_sort_least<<<1, 1024, 65536>>>(imp, noise);
    k_filter<<<BSROWS / 256, 256>>>();
    k_mapbuild<<<BSROWS / 256, 256>>>();
    k_bufprep<<<dim3(HD / 32, MSLOTS / 32), dim3(32, 8)>>>(membuf, hidden);

    // 3. q = h @ Wq^T + bq -> fp16
    gemm_h<<<dim3(HD / 256, BSROWS / 128), 256, 2 * STB>>>(
        (const __half*)p_hh, (const __half*)p_wqh, HD, HD, HD,
        bq, nullptr, 0, 1.0f, nullptr, (__half*)p_qh, HD, nullptr);

    // 4. mk = buf @ Wk^T + bk -> fp16
    gemm_h<<<dim3(HD / 256, MSLOTS / 128), 256, 2 * STB>>>(
        (const __half*)p_bufh, (const __half*)p_wkh, HD, HD, HD,
        bk, nullptr, 0, 1.0f, nullptr, (__half*)p_mkh, HD, nullptr);

    // 5. exp(scores) = exp(q @ mk^T / 32) -> fp16 + atomic rowsums
    gemm_h<<<dim3(MSLOTS / 256, BSROWS / 128), 256, 2 * STB>>>(
        (const __half*)p_qh, (const __half*)p_mkh, HD, HD, HD,
        nullptr, nullptr, 0, 0.03125f, nullptr, (__half*)p_attn, MSLOTS,
        (float*)p_rsum);

    // 6. retrieved = (exp @ buf) / rowsum -> d_out fp32 (recip rowscale fused)
    gemm_h<<<dim3(HD / 256, BSROWS / 128), 256, 2 * STB>>>(
        (const __half*)p_attn, (const __half*)p_bTh, MSLOTS, MSLOTS, MSLOTS,
        nullptr, (const float*)p_rsum, 1, 1.0f, out, nullptr, HD, nullptr);
}